// round 1
// baseline (speedup 1.0000x reference)
#include <cuda_runtime.h>

#define HH 256
#define N_NODES 8
#define N_EDGES 64
#define FEAT 1024

// Partial conv outputs: [half(2)][node(8)][oc(64)][128][128]  (67 MB)
__device__ float g_conv[(size_t)2 * 8 * 64 * 128 * 128];
// Pooled features: [edge(64)][ch(64)]
__device__ float g_pooled[N_EDGES * 64];

// ---------------------------------------------------------------------------
// Kernel 1: per-(node, weight-half) partial conv.  6->64 conv split into two
// 3->64 convs.  Output 128x128 per oc.  Block: 256 thr = 8 oc-groups x 32 px.
// Each thread: 8 output rows x 8 ocs = 64 fp32 accumulators.
// ---------------------------------------------------------------------------
__global__ __launch_bounds__(256) void conv_kernel(const float* __restrict__ x,
                                                   const float* __restrict__ w)
{
    __shared__ float s_w[49 * 64];          // weights for one input channel
    __shared__ float s_ine[3][21][36];      // even local columns
    __shared__ float s_ino[3][21][36];      // odd  local columns

    const int tid   = threadIdx.x;
    const int tileX = blockIdx.x;           // 0..3   (32 out cols each)
    const int tileY = blockIdx.y;           // 0..15  (8 out rows each)
    const int z     = blockIdx.z;           // 0..15
    const int node  = z & 7;
    const int half  = z >> 3;               // 0: weight ch 0..2, 1: ch 3..5

    // ---- stage input patch (all 3 image channels), zero-padded ----
    const int rbase = tileY * 16 - 3;
    const int cbase = tileX * 64 - 3;
    const float* xin = x + (size_t)node * (3 * HH * HH);
    for (int i = tid; i < 3 * 21 * 69; i += 256) {
        int ci  = i / (21 * 69);
        int rem = i - ci * (21 * 69);
        int r   = rem / 69;
        int L   = rem - r * 69;
        int gr = rbase + r, gc = cbase + L;
        float v = 0.f;
        if (gr >= 0 && gr < HH && gc >= 0 && gc < HH)
            v = xin[ci * HH * HH + gr * HH + gc];
        if (L & 1) s_ino[ci][r][L >> 1] = v;
        else       s_ine[ci][r][L >> 1] = v;
    }

    const int ocg = tid >> 5;   // 0..7  (oc group of 8)
    const int px  = tid & 31;   // output column within tile

    float acc[8][8];
    #pragma unroll
    for (int r = 0; r < 8; r++)
        #pragma unroll
        for (int c = 0; c < 8; c++) acc[r][c] = 0.f;

    for (int ci = 0; ci < 3; ci++) {
        __syncthreads();  // input staged / previous s_w readers done
        // stage weights for this input channel: s_w[(ky*7+kx)*64 + oc]
        for (int i = tid; i < 49 * 64; i += 256) {
            int k2 = i >> 6;
            int oc = i & 63;
            s_w[i] = w[(oc * 6 + half * 3 + ci) * 49 + k2];
        }
        __syncthreads();

        #pragma unroll 1
        for (int ky = 0; ky < 7; ky++) {
            #pragma unroll
            for (int kx = 0; kx < 7; kx++) {
                const float* wp = &s_w[(ky * 7 + kx) * 64 + ocg * 8];
                float4 wa = *(const float4*)wp;
                float4 wb = *(const float4*)(wp + 4);
                const float* src = (kx & 1) ? &s_ino[ci][0][0]
                                            : &s_ine[ci][0][0];
                const int cc = px + (kx >> 1);
                #pragma unroll
                for (int r = 0; r < 8; r++) {
                    float v = src[(2 * r + ky) * 36 + cc];
                    acc[r][0] += v * wa.x; acc[r][1] += v * wa.y;
                    acc[r][2] += v * wa.z; acc[r][3] += v * wa.w;
                    acc[r][4] += v * wb.x; acc[r][5] += v * wb.y;
                    acc[r][6] += v * wb.z; acc[r][7] += v * wb.w;
                }
            }
        }
    }

    // ---- write out ----
    float* outp = g_conv
        + ((size_t)(half * 8 + node) * 64 + ocg * 8) * 16384
        + (tileY * 8) * 128 + tileX * 32 + px;
    #pragma unroll
    for (int c = 0; c < 8; c++) {
        #pragma unroll
        for (int r = 0; r < 8; r++)
            outp[(size_t)c * 16384 + r * 128] = acc[r][c];
    }
}

// ---------------------------------------------------------------------------
// Kernel 2: per-(edge, channel) fused A+B -> BN -> ReLU -> maxpool3x3s2p1
//           -> spatial mean.   Two 65-row smem phases (stay <48KB static).
// ---------------------------------------------------------------------------
__global__ __launch_bounds__(256) void pool_kernel(
    const int*   __restrict__ edge_index,
    const float* __restrict__ gamma, const float* __restrict__ beta,
    const float* __restrict__ mean,  const float* __restrict__ var)
{
    __shared__ float s[65][132];
    __shared__ float s_red[8];

    const int c   = blockIdx.x;   // channel 0..63
    const int e   = blockIdx.y;   // edge 0..63
    const int tid = threadIdx.x;

    int a0 = edge_index[e], a1 = edge_index[N_EDGES + e];
    int nmin = min(a0, a1), nmax = max(a0, a1);

    float rs    = rsqrtf(var[c] + 1e-5f);
    float scale = gamma[c] * rs;
    float shift = beta[c] - mean[c] * scale;

    const float* pA = g_conv + ((size_t)(0 * 8 + nmin) * 64 + c) * 16384;
    const float* pB = g_conv + ((size_t)(1 * 8 + nmax) * 64 + c) * 16384;

    float sum = 0.f;

    for (int phase = 0; phase < 2; phase++) {
        __syncthreads();  // previous-phase readers done
        const int gbase = phase ? 63 : 0;
        const int sbase = phase ? 0 : 1;
        if (phase == 0)
            for (int j = tid; j < 132; j += 256) s[0][j] = 0.f;  // top pad row
        for (int rr = tid; rr < 65; rr += 256) { s[rr][0] = 0.f; s[rr][129] = 0.f; }

        const int nrows = phase ? 65 : 64;
        for (int i = tid; i < nrows * 32; i += 256) {
            int r  = i >> 5;
            int c4 = (i & 31) << 2;
            float4 a = *(const float4*)(pA + (gbase + r) * 128 + c4);
            float4 b = *(const float4*)(pB + (gbase + r) * 128 + c4);
            float* d = &s[sbase + r][1 + c4];
            d[0] = fmaxf((a.x + b.x) * scale + shift, 0.f);
            d[1] = fmaxf((a.y + b.y) * scale + shift, 0.f);
            d[2] = fmaxf((a.z + b.z) * scale + shift, 0.f);
            d[3] = fmaxf((a.w + b.w) * scale + shift, 0.f);
        }
        __syncthreads();

        // 32 pool-output rows per phase (outputs are 64x64 total)
        for (int i = tid; i < 2048; i += 256) {
            int pyl = i >> 6;
            int pxx = i & 63;
            int rb = 2 * pyl;
            int cb = 2 * pxx;
            float m =           s[rb    ][cb];
            m = fmaxf(m,        s[rb    ][cb + 1]);
            m = fmaxf(m,        s[rb    ][cb + 2]);
            m = fmaxf(m,        s[rb + 1][cb]);
            m = fmaxf(m,        s[rb + 1][cb + 1]);
            m = fmaxf(m,        s[rb + 1][cb + 2]);
            m = fmaxf(m,        s[rb + 2][cb]);
            m = fmaxf(m,        s[rb + 2][cb + 1]);
            m = fmaxf(m,        s[rb + 2][cb + 2]);
            sum += m;
        }
    }

    // block reduce
    #pragma unroll
    for (int o = 16; o > 0; o >>= 1) sum += __shfl_down_sync(0xffffffffu, sum, o);
    if ((tid & 31) == 0) s_red[tid >> 5] = sum;
    __syncthreads();
    if (tid == 0) {
        float t = 0.f;
        #pragma unroll
        for (int i = 0; i < 8; i++) t += s_red[i];
        g_pooled[e * 64 + c] = t * (1.f / 4096.f);
    }
}

// ---------------------------------------------------------------------------
// Kernel 3: fc(64->1024)+ReLU, then xyz/wpqr heads, write output layout
//           out[0:offs) = full[:offs/6],  out[offs:] = full  (offs = 48)
// ---------------------------------------------------------------------------
__global__ __launch_bounds__(256) void head_kernel(
    const float* __restrict__ fc_w,   const float* __restrict__ fc_b,
    const float* __restrict__ xyz_w,  const float* __restrict__ xyz_b,
    const float* __restrict__ wpqr_w, const float* __restrict__ wpqr_b,
    float* __restrict__ out, int out_size)
{
    __shared__ float s_p[64];
    __shared__ float s_f[FEAT];
    __shared__ float s_red[6][8];

    const int e   = blockIdx.x;
    const int tid = threadIdx.x;

    if (tid < 64) s_p[tid] = g_pooled[e * 64 + tid];
    __syncthreads();

    #pragma unroll
    for (int j = 0; j < 4; j++) {
        int f = tid + j * 256;
        float a = fc_b[f];
        const float* wr = fc_w + (size_t)f * 64;
        #pragma unroll 8
        for (int cc = 0; cc < 64; cc++) a += s_p[cc] * wr[cc];
        s_f[f] = fmaxf(a, 0.f);
    }
    __syncthreads();

    float p[6] = {0, 0, 0, 0, 0, 0};
    for (int f = tid; f < FEAT; f += 256) {
        float v = s_f[f];
        p[0] += v * xyz_w[f];
        p[1] += v * xyz_w[FEAT + f];
        p[2] += v * xyz_w[2 * FEAT + f];
        p[3] += v * wpqr_w[f];
        p[4] += v * wpqr_w[FEAT + f];
        p[5] += v * wpqr_w[2 * FEAT + f];
    }
    #pragma unroll
    for (int o = 0; o < 6; o++) {
        float v = p[o];
        #pragma unroll
        for (int sft = 16; sft > 0; sft >>= 1)
            v += __shfl_down_sync(0xffffffffu, v, sft);
        if ((tid & 31) == 0) s_red[o][tid >> 5] = v;
    }
    __syncthreads();
    if (tid < 6) {
        float t = 0.f;
        #pragma unroll
        for (int i = 0; i < 8; i++) t += s_red[tid][i];
        t += (tid < 3) ? xyz_b[tid] : wpqr_b[tid - 3];
        int offs = out_size - N_EDGES * 6;
        out[offs + e * 6 + tid] = t;
        if (e * 6 + tid < offs) out[e * 6 + tid] = t;
    }
}

// ---------------------------------------------------------------------------
extern "C" void kernel_launch(void* const* d_in, const int* in_sizes, int n_in,
                              void* d_out, int out_size)
{
    const float* x       = (const float*)d_in[0];
    const int*   ei      = (const int*)  d_in[1];
    const float* conv1_w = (const float*)d_in[2];
    const float* bn_g    = (const float*)d_in[3];
    const float* bn_b    = (const float*)d_in[4];
    const float* bn_m    = (const float*)d_in[5];
    const float* bn_v    = (const float*)d_in[6];
    const float* fc_w    = (const float*)d_in[7];
    const float* fc_b    = (const float*)d_in[8];
    const float* xyz_w   = (const float*)d_in[9];
    const float* xyz_b   = (const float*)d_in[10];
    const float* wpqr_w  = (const float*)d_in[11];
    const float* wpqr_b  = (const float*)d_in[12];
    float* out = (float*)d_out;

    conv_kernel<<<dim3(4, 16, 16), 256>>>(x, conv1_w);
    pool_kernel<<<dim3(64, 64), 256>>>(ei, bn_g, bn_b, bn_m, bn_v);
    head_kernel<<<N_EDGES, 256>>>(fc_w, fc_b, xyz_w, xyz_b, wpqr_w, wpqr_b,
                                  out, out_size);
}

// round 2
// speedup vs baseline: 1.1527x; 1.1527x over previous
#include <cuda_runtime.h>
#include <cuda_fp16.h>

#define HH 256
#define N_NODES 8
#define N_EDGES 64
#define FEAT 1024

// BN-folded partial conv outputs (fp16): [half(2)][node(8)][oc(64)][128][128]
__device__ __half g_convh[(size_t)2 * 8 * 64 * 128 * 128];
// Pooled features per node-pair: [pair(64: i*8+j)][ch(64)]
__device__ float g_pooled[64 * 64];

__device__ __forceinline__ unsigned long long pack2(float lo, float hi) {
    unsigned long long r;
    asm("mov.b64 %0, {%1, %2};" : "=l"(r) : "f"(lo), "f"(hi));
    return r;
}
__device__ __forceinline__ void unpack2(unsigned long long v, float& lo, float& hi) {
    asm("mov.b64 {%0, %1}, %2;" : "=f"(lo), "=f"(hi) : "l"(v));
}
__device__ __forceinline__ void ffma2(unsigned long long& d, unsigned long long a,
                                      unsigned long long b) {
    asm("fma.rn.f32x2 %0, %1, %2, %0;" : "+l"(d) : "l"(a), "l"(b));
}

// ---------------------------------------------------------------------------
// Kernel 1: per-(node, weight-half) partial conv with f32x2 packed FMA.
// 6->64 conv split into two 3->64 convs.  BN scale/shift folded into the
// epilogue, output stored as fp16.  Block: 256 thr = 8 oc-groups x 32 px.
// Each thread: 4 row-pairs x 8 ocs = 32 packed (64 fp32) accumulators.
// ---------------------------------------------------------------------------
__global__ __launch_bounds__(256) void conv_kernel(
    const float* __restrict__ x,    const float* __restrict__ w,
    const float* __restrict__ bn_g, const float* __restrict__ bn_b,
    const float* __restrict__ bn_m, const float* __restrict__ bn_v)
{
    __shared__ unsigned long long s_w2[49 * 64];  // (w,w) duplicated pairs, 25 KB
    __shared__ float s_ine[3][21][36];            // even local columns
    __shared__ float s_ino[3][21][36];            // odd  local columns

    const int tid   = threadIdx.x;
    const int tileX = blockIdx.x;           // 0..3   (32 out cols each)
    const int tileY = blockIdx.y;           // 0..15  (8 out rows each)
    const int z     = blockIdx.z;           // 0..15
    const int node  = z & 7;
    const int hf    = z >> 3;               // 0: weight ch 0..2, 1: ch 3..5

    // ---- stage input patch (all 3 image channels), zero-padded ----
    const int rbase = tileY * 16 - 3;
    const int cbase = tileX * 64 - 3;
    const float* xin = x + (size_t)node * (3 * HH * HH);
    for (int i = tid; i < 3 * 21 * 69; i += 256) {
        int ci  = i / (21 * 69);
        int rem = i - ci * (21 * 69);
        int r   = rem / 69;
        int L   = rem - r * 69;
        int gr = rbase + r, gc = cbase + L;
        float v = 0.f;
        if (gr >= 0 && gr < HH && gc >= 0 && gc < HH)
            v = xin[ci * HH * HH + gr * HH + gc];
        if (L & 1) s_ino[ci][r][L >> 1] = v;
        else       s_ine[ci][r][L >> 1] = v;
    }

    const int ocg = tid >> 5;   // 0..7  (oc group of 8) — warp-uniform
    const int px  = tid & 31;   // output column within tile

    unsigned long long acc2[4][8];   // [row-pair][oc], lo=row 2rp, hi=row 2rp+1
    #pragma unroll
    for (int rp = 0; rp < 4; rp++)
        #pragma unroll
        for (int c = 0; c < 8; c++) acc2[rp][c] = 0ull;

    for (int ci = 0; ci < 3; ci++) {
        __syncthreads();  // input staged / previous s_w2 readers done
        // stage duplicated weights: s_w2[k2*64+oc] = (w,w)
        for (int i = tid; i < 49 * 64; i += 256) {
            int k2 = i >> 6;
            int oc = i & 63;
            float wv = w[(oc * 6 + hf * 3 + ci) * 49 + k2];
            s_w2[i] = pack2(wv, wv);
        }
        __syncthreads();

        #pragma unroll 1
        for (int ky = 0; ky < 7; ky++) {
            #pragma unroll
            for (int kx = 0; kx < 7; kx++) {
                const unsigned long long* wp = &s_w2[(ky * 7 + kx) * 64 + ocg * 8];
                ulonglong2 w01 = ((const ulonglong2*)wp)[0];
                ulonglong2 w23 = ((const ulonglong2*)wp)[1];
                ulonglong2 w45 = ((const ulonglong2*)wp)[2];
                ulonglong2 w67 = ((const ulonglong2*)wp)[3];
                const float* src = (kx & 1) ? &s_ino[ci][0][0]
                                            : &s_ine[ci][0][0];
                const int cc = px + (kx >> 1);
                #pragma unroll
                for (int rp = 0; rp < 4; rp++) {
                    float v0 = src[(4 * rp + ky) * 36 + cc];       // out row 2rp
                    float v1 = src[(4 * rp + 2 + ky) * 36 + cc];   // out row 2rp+1
                    unsigned long long vp = pack2(v0, v1);
                    ffma2(acc2[rp][0], vp, w01.x); ffma2(acc2[rp][1], vp, w01.y);
                    ffma2(acc2[rp][2], vp, w23.x); ffma2(acc2[rp][3], vp, w23.y);
                    ffma2(acc2[rp][4], vp, w45.x); ffma2(acc2[rp][5], vp, w45.y);
                    ffma2(acc2[rp][6], vp, w67.x); ffma2(acc2[rp][7], vp, w67.y);
                }
            }
        }
    }

    // ---- epilogue: fold BN, store fp16 ----
    __half* outp = g_convh
        + ((size_t)(hf * 8 + node) * 64 + ocg * 8) * 16384
        + (tileY * 8) * 128 + tileX * 32 + px;
    #pragma unroll
    for (int c = 0; c < 8; c++) {
        int oc = ocg * 8 + c;
        float rs = rsqrtf(bn_v[oc] + 1e-5f);
        float sc = bn_g[oc] * rs;
        float sh = hf ? (bn_b[oc] - bn_m[oc] * sc) : 0.f;
        #pragma unroll
        for (int rp = 0; rp < 4; rp++) {
            float lo, hi;
            unpack2(acc2[rp][c], lo, hi);
            outp[(size_t)c * 16384 + (2 * rp) * 128]     = __float2half_rn(lo * sc + sh);
            outp[(size_t)c * 16384 + (2 * rp + 1) * 128] = __float2half_rn(hi * sc + sh);
        }
    }
}

// ---------------------------------------------------------------------------
// Kernel 2: per-(pair, channel) fused A+B -> ReLU -> maxpool3x3s2p1 -> mean.
// BN already folded into g_convh.  36 unordered node pairs (i<=j).
// Two 65-row smem phases.
// ---------------------------------------------------------------------------
__global__ __launch_bounds__(256) void pool_kernel()
{
    __shared__ float s[65][132];
    __shared__ float s_red[8];

    const int c   = blockIdx.x;   // channel 0..63
    const int tid = threadIdx.x;

    // pair index -> (i, j) with i <= j
    int p = blockIdx.y;           // 0..35
    int i = 0, base = 0;
    while (p >= base + (8 - i)) { base += 8 - i; i++; }
    int j = i + (p - base);

    const __half* pA = g_convh + ((size_t)(0 * 8 + i) * 64 + c) * 16384;
    const __half* pB = g_convh + ((size_t)(1 * 8 + j) * 64 + c) * 16384;

    float sum = 0.f;

    for (int phase = 0; phase < 2; phase++) {
        __syncthreads();  // previous-phase readers done
        const int gbase = phase ? 63 : 0;
        const int sbase = phase ? 0 : 1;
        if (phase == 0)
            for (int q = tid; q < 132; q += 256) s[0][q] = 0.f;  // top pad row
        for (int rr = tid; rr < 65; rr += 256) { s[rr][0] = 0.f; s[rr][129] = 0.f; }

        const int nrows = phase ? 65 : 64;
        for (int t = tid; t < nrows * 16; t += 256) {
            int r  = t >> 4;
            int c8 = (t & 15) << 3;
            float4 av = *(const float4*)(pA + (gbase + r) * 128 + c8);  // 8 halfs
            float4 bv = *(const float4*)(pB + (gbase + r) * 128 + c8);
            const __half2* ah = (const __half2*)&av;
            const __half2* bh = (const __half2*)&bv;
            float* d = &s[sbase + r][1 + c8];
            #pragma unroll
            for (int q = 0; q < 4; q++) {
                float2 fa = __half22float2(ah[q]);
                float2 fb = __half22float2(bh[q]);
                d[2 * q]     = fmaxf(fa.x + fb.x, 0.f);
                d[2 * q + 1] = fmaxf(fa.y + fb.y, 0.f);
            }
        }
        __syncthreads();

        // 32 pool-output rows per phase (outputs are 64x64 total)
        for (int t = tid; t < 2048; t += 256) {
            int pyl = t >> 6;
            int pxx = t & 63;
            int rb = 2 * pyl;
            int cb = 2 * pxx;
            float m =    s[rb    ][cb];
            m = fmaxf(m, s[rb    ][cb + 1]);
            m = fmaxf(m, s[rb    ][cb + 2]);
            m = fmaxf(m, s[rb + 1][cb]);
            m = fmaxf(m, s[rb + 1][cb + 1]);
            m = fmaxf(m, s[rb + 1][cb + 2]);
            m = fmaxf(m, s[rb + 2][cb]);
            m = fmaxf(m, s[rb + 2][cb + 1]);
            m = fmaxf(m, s[rb + 2][cb + 2]);
            sum += m;
        }
    }

    // block reduce
    #pragma unroll
    for (int o = 16; o > 0; o >>= 1) sum += __shfl_down_sync(0xffffffffu, sum, o);
    if ((tid & 31) == 0) s_red[tid >> 5] = sum;
    __syncthreads();
    if (tid == 0) {
        float t = 0.f;
        #pragma unroll
        for (int q = 0; q < 8; q++) t += s_red[q];
        g_pooled[(i * 8 + j) * 64 + c] = t * (1.f / 4096.f);
    }
}

// ---------------------------------------------------------------------------
// Kernel 3: fc(64->1024)+ReLU, then xyz/wpqr heads, write output layout
//           out[0:offs) = full[:offs/6],  out[offs:] = full  (offs = 48)
// ---------------------------------------------------------------------------
__global__ __launch_bounds__(256) void head_kernel(
    const int*   __restrict__ edge_index,
    const float* __restrict__ fc_w,   const float* __restrict__ fc_b,
    const float* __restrict__ xyz_w,  const float* __restrict__ xyz_b,
    const float* __restrict__ wpqr_w, const float* __restrict__ wpqr_b,
    float* __restrict__ out, int out_size)
{
    __shared__ float s_p[64];
    __shared__ float s_f[FEAT];
    __shared__ float s_red[6][8];

    const int e   = blockIdx.x;
    const int tid = threadIdx.x;

    int a0 = edge_index[e], a1 = edge_index[N_EDGES + e];
    int nmin = min(a0, a1), nmax = max(a0, a1);

    if (tid < 64) s_p[tid] = g_pooled[(nmin * 8 + nmax) * 64 + tid];
    __syncthreads();

    #pragma unroll
    for (int jj = 0; jj < 4; jj++) {
        int f = tid + jj * 256;
        float a = fc_b[f];
        const float* wr = fc_w + (size_t)f * 64;
        #pragma unroll 8
        for (int cc = 0; cc < 64; cc++) a += s_p[cc] * wr[cc];
        s_f[f] = fmaxf(a, 0.f);
    }
    __syncthreads();

    float p[6] = {0, 0, 0, 0, 0, 0};
    for (int f = tid; f < FEAT; f += 256) {
        float v = s_f[f];
        p[0] += v * xyz_w[f];
        p[1] += v * xyz_w[FEAT + f];
        p[2] += v * xyz_w[2 * FEAT + f];
        p[3] += v * wpqr_w[f];
        p[4] += v * wpqr_w[FEAT + f];
        p[5] += v * wpqr_w[2 * FEAT + f];
    }
    #pragma unroll
    for (int o = 0; o < 6; o++) {
        float v = p[o];
        #pragma unroll
        for (int sft = 16; sft > 0; sft >>= 1)
            v += __shfl_down_sync(0xffffffffu, v, sft);
        if ((tid & 31) == 0) s_red[o][tid >> 5] = v;
    }
    __syncthreads();
    if (tid < 6) {
        float t = 0.f;
        #pragma unroll
        for (int q = 0; q < 8; q++) t += s_red[tid][q];
        t += (tid < 3) ? xyz_b[tid] : wpqr_b[tid - 3];
        int offs = out_size - N_EDGES * 6;
        out[offs + e * 6 + tid] = t;
        if (e * 6 + tid < offs) out[e * 6 + tid] = t;
    }
}

// ---------------------------------------------------------------------------
extern "C" void kernel_launch(void* const* d_in, const int* in_sizes, int n_in,
                              void* d_out, int out_size)
{
    const float* x       = (const float*)d_in[0];
    const int*   ei      = (const int*)  d_in[1];
    const float* conv1_w = (const float*)d_in[2];
    const float* bn_g    = (const float*)d_in[3];
    const float* bn_b    = (const float*)d_in[4];
    const float* bn_m    = (const float*)d_in[5];
    const float* bn_v    = (const float*)d_in[6];
    const float* fc_w    = (const float*)d_in[7];
    const float* fc_b    = (const float*)d_in[8];
    const float* xyz_w   = (const float*)d_in[9];
    const float* xyz_b   = (const float*)d_in[10];
    const float* wpqr_w  = (const float*)d_in[11];
    const float* wpqr_b  = (const float*)d_in[12];
    float* out = (float*)d_out;

    conv_kernel<<<dim3(4, 16, 16), 256>>>(x, conv1_w, bn_g, bn_b, bn_m, bn_v);
    pool_kernel<<<dim3(64, 36), 256>>>();
    head_kernel<<<N_EDGES, 256>>>(ei, fc_w, fc_b, xyz_w, xyz_b,
                                  wpqr_w, wpqr_b, out, out_size);
}

// round 5
// speedup vs baseline: 1.4511x; 1.2589x over previous
#include <cuda_runtime.h>
#include <cuda_fp16.h>
#include <cstdint>
#include <cstring>

#define HH 256
#define N_NODES 8
#define N_EDGES 64
#define FEAT 1024

#define KDIM 192            // 147 real taps padded to 3 x 64
#define KREAL 147
#define NPX 16384           // 128x128 output plane

// im2col activations (fp16): [node(8)][px(16384)][k(192)]
__device__ __half g_xcol[(size_t)N_NODES * NPX * KDIM];
// repacked weights (fp16): [oc2(128)][k(192)]   oc2 = half*64 + oc
__device__ __half g_wcol[128 * KDIM];
// BN-folded partial conv outputs (fp16): [half(2)][node(8)][oc(64)][128][128]
__device__ __half g_convh[(size_t)2 * 8 * 64 * 128 * 128];
// Pooled features per node-pair: [pair i*8+j][ch(64)]
__device__ float g_pooled[64 * 64];

__device__ __forceinline__ uint32_t smem_u32(const void* p) {
    uint32_t a;
    asm("{ .reg .u64 t; cvta.to.shared.u64 t, %1; cvt.u32.u64 %0, t; }"
        : "=r"(a) : "l"(p));
    return a;
}
__device__ __forceinline__ uint32_t sw128(uint32_t o) { return o ^ ((o >> 3) & 0x70); }

__device__ __forceinline__ void ldsm_x4(uint32_t& r0, uint32_t& r1,
                                        uint32_t& r2, uint32_t& r3, uint32_t a) {
    asm volatile("ldmatrix.sync.aligned.m8n8.x4.shared.b16 {%0,%1,%2,%3}, [%4];"
                 : "=r"(r0), "=r"(r1), "=r"(r2), "=r"(r3) : "r"(a));
}
__device__ __forceinline__ void mma16816(float* c, const uint32_t* a,
                                         const uint32_t* b) {
    asm volatile("mma.sync.aligned.m16n8k16.row.col.f32.f16.f16.f32 "
                 "{%0,%1,%2,%3}, {%4,%5,%6,%7}, {%8,%9}, {%0,%1,%2,%3};"
                 : "+f"(c[0]), "+f"(c[1]), "+f"(c[2]), "+f"(c[3])
                 : "r"(a[0]), "r"(a[1]), "r"(a[2]), "r"(a[3]),
                   "r"(b[0]), "r"(b[1]));
}

// ---------------------------------------------------------------------------
// Kernel 0a: im2col. Each thread writes one u32 (2 fp16 k-values).
// ---------------------------------------------------------------------------
__global__ __launch_bounds__(256) void im2col_kernel(const float* __restrict__ x)
{
    int idx = blockIdx.x * 256 + threadIdx.x;        // [0, 8*16384*96)
    int kp  = idx % 96;
    int row = idx / 96;
    int node = row >> 14;
    int px   = row & 16383;
    int py   = px >> 7;
    int pxx  = px & 127;

    float v[2];
    #pragma unroll
    for (int q = 0; q < 2; q++) {
        int k = 2 * kp + q;
        float val = 0.f;
        if (k < KREAL) {
            int ci  = k / 49;
            int rem = k - ci * 49;
            int ky  = rem / 7;
            int kx  = rem - ky * 7;
            int r = 2 * py - 3 + ky;
            int c = 2 * pxx - 3 + kx;
            if (r >= 0 && r < HH && c >= 0 && c < HH)
                val = x[((size_t)(node * 3 + ci) * HH + r) * HH + c];
        }
        v[q] = val;
    }
    __half2 h2 = __floats2half2_rn(v[0], v[1]);
    uint32_t bits;
    memcpy(&bits, &h2, 4);
    ((uint32_t*)g_xcol)[(size_t)row * 96 + kp] = bits;
}

// ---------------------------------------------------------------------------
// Kernel 0b: weight repack. Wcol[oc2][k], pad->0.
// ---------------------------------------------------------------------------
__global__ __launch_bounds__(256) void wrepack_kernel(const float* __restrict__ w)
{
    for (int i = blockIdx.x * 256 + threadIdx.x; i < 128 * KDIM;
         i += gridDim.x * 256) {
        int oc2 = i / KDIM;
        int k   = i - oc2 * KDIM;
        int hf  = oc2 >> 6;
        int oc  = oc2 & 63;
        float val = 0.f;
        if (k < KREAL) {
            int ci = k / 49;
            int k2 = k - ci * 49;
            val = w[(oc * 6 + hf * 3 + ci) * 49 + k2];
        }
        g_wcol[i] = __float2half_rn(val);
    }
}

// ---------------------------------------------------------------------------
// Kernel 1: HMMA GEMM via mma.sync m16n8k16.  CTA: M=128 px, N=128 oc2,
// K=192 (3 chunks of 64, staged SW128 in smem).  8 warps = 2(m) x 4(n),
// warp tile 64x32.  Epilogue folds BN, stores fp16 into g_convh.
// ---------------------------------------------------------------------------
__global__ __launch_bounds__(256) void gemm_kernel(
    const float* __restrict__ bn_g, const float* __restrict__ bn_b,
    const float* __restrict__ bn_m, const float* __restrict__ bn_v)
{
    __shared__ __align__(128) char s_a[16384];   // A chunk 128 x 64 fp16 SW128
    __shared__ __align__(128) char s_b[16384];   // B chunk 128 x 64 fp16 SW128
    __shared__ float s_sc[128], s_sh[128];

    const int tid  = threadIdx.x;
    const int wid  = tid >> 5;
    const int lid  = tid & 31;
    const int tile = blockIdx.x;          // px tile (0..127)
    const int node = blockIdx.y;

    if (tid < 128) {
        int hf = tid >> 6, oc = tid & 63;
        float rs = rsqrtf(bn_v[oc] + 1e-5f);
        float sc = bn_g[oc] * rs;
        s_sc[tid] = sc;
        s_sh[tid] = hf ? (bn_b[oc] - bn_m[oc] * sc) : 0.f;
    }

    const int warp_m = wid >> 2;          // 0..1  (64 rows)
    const int warp_n = wid & 3;           // 0..3  (32 cols)

    const uint32_t sa = smem_u32(s_a);
    const uint32_t sb = smem_u32(s_b);

    float acc[4][4][4];                   // [m-tile][n-tile][reg]
    #pragma unroll
    for (int mt = 0; mt < 4; mt++)
        #pragma unroll
        for (int nt = 0; nt < 4; nt++)
            #pragma unroll
            for (int q = 0; q < 4; q++) acc[mt][nt][q] = 0.f;

    const __half* Arow = g_xcol + (size_t)(node * NPX + tile * 128) * KDIM;

    // precomputed ldmatrix lane addressing
    const int a_row = warp_m * 64 + (lid & 15);       // + mt*16
    const int a_kbh = lid >> 4;                       // kb = s*2 + a_kbh
    const int b_row = warp_n * 32 + (lid & 7) + ((lid >> 4) << 3);  // + np*16
    const int b_kbh = (lid >> 3) & 1;

    for (int ck = 0; ck < 3; ck++) {
        __syncthreads();   // previous chunk consumed
        #pragma unroll
        for (int i = 0; i < 4; i++) {
            int idx = i * 256 + tid;      // 0..1023
            int g = idx & 7, r = idx >> 3;
            uint4 va = *(const uint4*)(Arow + (size_t)r * KDIM + ck * 64 + g * 8);
            *(uint4*)(s_a + sw128(r * 128 + g * 16)) = va;
            uint4 vb = *(const uint4*)(g_wcol + (size_t)r * KDIM + ck * 64 + g * 8);
            *(uint4*)(s_b + sw128(r * 128 + g * 16)) = vb;
        }
        __syncthreads();

        #pragma unroll
        for (int s = 0; s < 4; s++) {     // k16 steps within chunk
            // B fragments: 2 x ldmatrix.x4 cover 4 n-tiles
            uint32_t bf[4][2];
            #pragma unroll
            for (int np = 0; np < 2; np++) {
                uint32_t addr = sb + sw128((b_row + np * 16) * 128
                                           + (s * 2 + b_kbh) * 16);
                uint32_t r0, r1, r2, r3;
                ldsm_x4(r0, r1, r2, r3, addr);
                bf[np * 2][0] = r0;     bf[np * 2][1] = r1;
                bf[np * 2 + 1][0] = r2; bf[np * 2 + 1][1] = r3;
            }
            #pragma unroll
            for (int mt = 0; mt < 4; mt++) {
                uint32_t af[4];
                uint32_t addr = sa + sw128((a_row + mt * 16) * 128
                                           + (s * 2 + a_kbh) * 16);
                ldsm_x4(af[0], af[1], af[2], af[3], addr);
                #pragma unroll
                for (int nt = 0; nt < 4; nt++)
                    mma16816(acc[mt][nt], af, bf[nt]);
            }
        }
    }

    // ---- epilogue: BN fold -> fp16 g_convh ----
    const int g   = lid >> 2;
    const int tig = lid & 3;
    const int px0 = tile * 128 + warp_m * 64 + g;

    #pragma unroll
    for (int nt = 0; nt < 4; nt++) {
        int oc2a = warp_n * 32 + nt * 8 + tig * 2;
        #pragma unroll
        for (int half_c = 0; half_c < 2; half_c++) {
            int oc2 = oc2a + half_c;
            float sc = s_sc[oc2], sh = s_sh[oc2];
            int hf = oc2 >> 6, oc = oc2 & 63;
            __half* base = g_convh + ((size_t)(hf * 8 + node) * 64 + oc) * NPX;
            #pragma unroll
            for (int mt = 0; mt < 4; mt++) {
                int px = px0 + mt * 16;
                base[px]     = __float2half_rn(acc[mt][nt][half_c]     * sc + sh);
                base[px + 8] = __float2half_rn(acc[mt][nt][half_c + 2] * sc + sh);
            }
        }
    }
}

// ---------------------------------------------------------------------------
// Kernel 2: per-(pair, channel) fused A+B -> ReLU -> maxpool3x3s2p1 -> mean.
// ---------------------------------------------------------------------------
__global__ __launch_bounds__(256) void pool_kernel()
{
    __shared__ float s[65][132];
    __shared__ float s_red[8];

    const int c   = blockIdx.x;
    const int tid = threadIdx.x;

    int p = blockIdx.y;           // 0..35 -> (i, j), i <= j
    int i = 0, base = 0;
    while (p >= base + (8 - i)) { base += 8 - i; i++; }
    int j = i + (p - base);

    const __half* pA = g_convh + ((size_t)(0 * 8 + i) * 64 + c) * NPX;
    const __half* pB = g_convh + ((size_t)(1 * 8 + j) * 64 + c) * NPX;

    float sum = 0.f;

    for (int phase = 0; phase < 2; phase++) {
        __syncthreads();
        const int gbase = phase ? 63 : 0;
        const int sbase2 = phase ? 0 : 1;
        if (phase == 0)
            for (int q = tid; q < 132; q += 256) s[0][q] = 0.f;
        for (int rr = tid; rr < 65; rr += 256) { s[rr][0] = 0.f; s[rr][129] = 0.f; }

        const int nrows = phase ? 65 : 64;
        for (int t = tid; t < nrows * 16; t += 256) {
            int r  = t >> 4;
            int c8 = (t & 15) << 3;
            float4 av = *(const float4*)(pA + (gbase + r) * 128 + c8);
            float4 bv = *(const float4*)(pB + (gbase + r) * 128 + c8);
            const __half2* ah = (const __half2*)&av;
            const __half2* bh = (const __half2*)&bv;
            float* d = &s[sbase2 + r][1 + c8];
            #pragma unroll
            for (int q = 0; q < 4; q++) {
                float2 fa = __half22float2(ah[q]);
                float2 fb = __half22float2(bh[q]);
                d[2 * q]     = fmaxf(fa.x + fb.x, 0.f);
                d[2 * q + 1] = fmaxf(fa.y + fb.y, 0.f);
            }
        }
        __syncthreads();

        for (int t = tid; t < 2048; t += 256) {
            int pyl = t >> 6;
            int pxx = t & 63;
            int rb = 2 * pyl, cb = 2 * pxx;
            float m =    s[rb    ][cb];
            m = fmaxf(m, s[rb    ][cb + 1]);
            m = fmaxf(m, s[rb    ][cb + 2]);
            m = fmaxf(m, s[rb + 1][cb]);
            m = fmaxf(m, s[rb + 1][cb + 1]);
            m = fmaxf(m, s[rb + 1][cb + 2]);
            m = fmaxf(m, s[rb + 2][cb]);
            m = fmaxf(m, s[rb + 2][cb + 1]);
            m = fmaxf(m, s[rb + 2][cb + 2]);
            sum += m;
        }
    }

    #pragma unroll
    for (int o = 16; o > 0; o >>= 1) sum += __shfl_down_sync(0xffffffffu, sum, o);
    if ((tid & 31) == 0) s_red[tid >> 5] = sum;
    __syncthreads();
    if (tid == 0) {
        float t = 0.f;
        #pragma unroll
        for (int q = 0; q < 8; q++) t += s_red[q];
        g_pooled[(i * 8 + j) * 64 + c] = t * (1.f / 4096.f);
    }
}

// ---------------------------------------------------------------------------
// Kernel 3: fc(64->1024)+ReLU, xyz/wpqr heads.
// ---------------------------------------------------------------------------
__global__ __launch_bounds__(256) void head_kernel(
    const int*   __restrict__ edge_index,
    const float* __restrict__ fc_w,   const float* __restrict__ fc_b,
    const float* __restrict__ xyz_w,  const float* __restrict__ xyz_b,
    const float* __restrict__ wpqr_w, const float* __restrict__ wpqr_b,
    float* __restrict__ out, int out_size)
{
    __shared__ float s_p[64];
    __shared__ float s_f[FEAT];
    __shared__ float s_red[6][8];

    const int e   = blockIdx.x;
    const int tid = threadIdx.x;

    int a0 = edge_index[e], a1 = edge_index[N_EDGES + e];
    int nmin = min(a0, a1), nmax = max(a0, a1);

    if (tid < 64) s_p[tid] = g_pooled[(nmin * 8 + nmax) * 64 + tid];
    __syncthreads();

    #pragma unroll
    for (int jj = 0; jj < 4; jj++) {
        int f = tid + jj * 256;
        float a = fc_b[f];
        const float* wr = fc_w + (size_t)f * 64;
        #pragma unroll 8
        for (int cc = 0; cc < 64; cc++) a += s_p[cc] * wr[cc];
        s_f[f] = fmaxf(a, 0.f);
    }
    __syncthreads();

    float p[6] = {0, 0, 0, 0, 0, 0};
    for (int f = tid; f < FEAT; f += 256) {
        float v = s_f[f];
        p[0] += v * xyz_w[f];
        p[1] += v * xyz_w[FEAT + f];
        p[2] += v * xyz_w[2 * FEAT + f];
        p[3] += v * wpqr_w[f];
        p[4] += v * wpqr_w[FEAT + f];
        p[5] += v * wpqr_w[2 * FEAT + f];
    }
    #pragma unroll
    for (int o = 0; o < 6; o++) {
        float v = p[o];
        #pragma unroll
        for (int sft = 16; sft > 0; sft >>= 1)
            v += __shfl_down_sync(0xffffffffu, v, sft);
        if ((tid & 31) == 0) s_red[o][tid >> 5] = v;
    }
    __syncthreads();
    if (tid < 6) {
        float t = 0.f;
        #pragma unroll
        for (int q = 0; q < 8; q++) t += s_red[tid][q];
        t += (tid < 3) ? xyz_b[tid] : wpqr_b[tid - 3];
        int offs = out_size - N_EDGES * 6;
        out[offs + e * 6 + tid] = t;
        if (e * 6 + tid < offs) out[e * 6 + tid] = t;
    }
}

// ---------------------------------------------------------------------------
extern "C" void kernel_launch(void* const* d_in, const int* in_sizes, int n_in,
                              void* d_out, int out_size)
{
    const float* x       = (const float*)d_in[0];
    const int*   ei      = (const int*)  d_in[1];
    const float* conv1_w = (const float*)d_in[2];
    const float* bn_g    = (const float*)d_in[3];
    const float* bn_b    = (const float*)d_in[4];
    const float* bn_m    = (const float*)d_in[5];
    const float* bn_v    = (const float*)d_in[6];
    const float* fc_w    = (const float*)d_in[7];
    const float* fc_b    = (const float*)d_in[8];
    const float* xyz_w   = (const float*)d_in[9];
    const float* xyz_b   = (const float*)d_in[10];
    const float* wpqr_w  = (const float*)d_in[11];
    const float* wpqr_b  = (const float*)d_in[12];
    float* out = (float*)d_out;

    im2col_kernel<<<(N_NODES * NPX * 96) / 256, 256>>>(x);
    wrepack_kernel<<<96, 256>>>(conv1_w);
    gemm_kernel<<<dim3(128, 8), 256>>>(bn_g, bn_b, bn_m, bn_v);
    pool_kernel<<<dim3(64, 36), 256>>>();
    head_kernel<<<N_EDGES, 256>>>(ei, fc_w, fc_b, xyz_w, xyz_b,
                                  wpqr_w, wpqr_b, out, out_size);
}

// round 6
// speedup vs baseline: 1.9111x; 1.3170x over previous
#include <cuda_runtime.h>
#include <cuda_fp16.h>
#include <cstdint>
#include <cstring>

#define HH 256
#define N_NODES 8
#define N_EDGES 64
#define FEAT 1024

#define KDIM 160            // 147 real taps padded to 10 k16-steps
#define KREAL 147
#define NPX 16384           // 128x128 output plane

// im2col activations (fp16): [node(8)][px(16384)][k(160)]
__device__ __half g_xcol[(size_t)N_NODES * NPX * KDIM];
// repacked weights (fp16): [oc2(128)][k(160)]   oc2 = half*64 + oc
__device__ __half g_wcol[128 * KDIM];
// BN-folded partial conv outputs (fp16): [half(2)][node(8)][oc(64)][128][128]
__device__ __half g_convh[(size_t)2 * 8 * 64 * 128 * 128];
// Pooled features per node-pair: [pair i*8+j][ch(64)]
__device__ float g_pooled[64 * 64];

__device__ __forceinline__ uint32_t smem_u32(const void* p) {
    uint32_t a;
    asm("{ .reg .u64 t; cvta.to.shared.u64 t, %1; cvt.u32.u64 %0, t; }"
        : "=r"(a) : "l"(p));
    return a;
}
__device__ __forceinline__ uint32_t sw128(uint32_t o) { return o ^ ((o >> 3) & 0x70); }

__device__ __forceinline__ void ldsm_x4(uint32_t& r0, uint32_t& r1,
                                        uint32_t& r2, uint32_t& r3, uint32_t a) {
    asm volatile("ldmatrix.sync.aligned.m8n8.x4.shared.b16 {%0,%1,%2,%3}, [%4];"
                 : "=r"(r0), "=r"(r1), "=r"(r2), "=r"(r3) : "r"(a));
}
__device__ __forceinline__ void mma16816(float* c, const uint32_t* a,
                                         const uint32_t* b) {
    asm volatile("mma.sync.aligned.m16n8k16.row.col.f32.f16.f16.f32 "
                 "{%0,%1,%2,%3}, {%4,%5,%6,%7}, {%8,%9}, {%0,%1,%2,%3};"
                 : "+f"(c[0]), "+f"(c[1]), "+f"(c[2]), "+f"(c[3])
                 : "r"(a[0]), "r"(a[1]), "r"(a[2]), "r"(a[3]),
                   "r"(b[0]), "r"(b[1]));
}

// ---------------------------------------------------------------------------
// Kernel 0a: im2col via smem-staged input slab.
// Block = (py, node).  Stage 3ch x 7 rows x 264 cols fp16 in smem, then each
// thread owns a fixed tap-pair kp (decomposed once) and sweeps px.
// ---------------------------------------------------------------------------
__global__ __launch_bounds__(320) void im2col_kernel(const float* __restrict__ x)
{
    __shared__ __half s_in[3][7][264];    // col index = global col + 3

    const int py   = blockIdx.x;          // output row 0..127
    const int node = blockIdx.y;
    const int tid  = threadIdx.y * 80 + threadIdx.x;

    // stage input rows 2py-3 .. 2py+3, cols -3..260, zero-padded
    for (int i = tid; i < 3 * 7 * 264; i += 320) {
        int ci  = i / (7 * 264);
        int rem = i - ci * (7 * 264);
        int ry  = rem / 264;
        int cc  = rem - ry * 264;
        int r = 2 * py - 3 + ry;
        int c = cc - 3;
        float v = 0.f;
        if (r >= 0 && r < HH && c >= 0 && c < HH)
            v = x[((size_t)(node * 3 + ci) * HH + r) * HH + c];
        s_in[ci][ry][cc] = __float2half_rn(v);
    }
    __syncthreads();

    const int kp = threadIdx.x;           // 0..79 -> k pair (2kp, 2kp+1)
    int k0 = 2 * kp, k1 = 2 * kp + 1;
    int ci0 = 0, ky0 = 0, kx0 = 0, ci1 = 0, ky1 = 0, kx1 = 0;
    bool v0ok = k0 < KREAL, v1ok = k1 < KREAL;
    if (v0ok) { ci0 = k0 / 49; int r = k0 - ci0 * 49; ky0 = r / 7; kx0 = r - ky0 * 7; }
    if (v1ok) { ci1 = k1 / 49; int r = k1 - ci1 * 49; ky1 = r / 7; kx1 = r - ky1 * 7; }

    uint32_t* orow = (uint32_t*)g_xcol + (size_t)(node * NPX + py * 128) * 80 + kp;
    for (int pxx = threadIdx.y; pxx < 128; pxx += 4) {
        __half h0 = v0ok ? s_in[ci0][ky0][2 * pxx + kx0] : __float2half_rn(0.f);
        __half h1 = v1ok ? s_in[ci1][ky1][2 * pxx + kx1] : __float2half_rn(0.f);
        __half2 h2 = __halves2half2(h0, h1);
        uint32_t bits;
        memcpy(&bits, &h2, 4);
        orow[(size_t)pxx * 80] = bits;
    }
}

// ---------------------------------------------------------------------------
// Kernel 0b: weight repack. Wcol[oc2][k], pad->0.
// ---------------------------------------------------------------------------
__global__ __launch_bounds__(256) void wrepack_kernel(const float* __restrict__ w)
{
    for (int i = blockIdx.x * 256 + threadIdx.x; i < 128 * KDIM;
         i += gridDim.x * 256) {
        int oc2 = i / KDIM;
        int k   = i - oc2 * KDIM;
        int hf  = oc2 >> 6;
        int oc  = oc2 & 63;
        float val = 0.f;
        if (k < KREAL) {
            int ci = k / 49;
            int k2 = k - ci * 49;
            val = w[(oc * 6 + hf * 3 + ci) * 49 + k2];
        }
        g_wcol[i] = __float2half_rn(val);
    }
}

// ---------------------------------------------------------------------------
// Kernel 1: HMMA GEMM via mma.sync m16n8k16.  CTA: M=128 px, N=128 oc2,
// K=160 (2 chunks of 64 + 1 chunk of 32, staged SW128).  8 warps = 2x4,
// warp tile 64x32.  Epilogue folds BN, stores fp16 into g_convh.
// ---------------------------------------------------------------------------
__global__ __launch_bounds__(256) void gemm_kernel(
    const float* __restrict__ bn_g, const float* __restrict__ bn_b,
    const float* __restrict__ bn_m, const float* __restrict__ bn_v)
{
    __shared__ __align__(128) char s_a[16384];   // A chunk 128 x 64 fp16 SW128
    __shared__ __align__(128) char s_b[16384];   // B chunk 128 x 64 fp16 SW128
    __shared__ float s_sc[128], s_sh[128];

    const int tid  = threadIdx.x;
    const int wid  = tid >> 5;
    const int lid  = tid & 31;
    const int tile = blockIdx.x;          // px tile (0..127)
    const int node = blockIdx.y;

    if (tid < 128) {
        int hf = tid >> 6, oc = tid & 63;
        float rs = rsqrtf(bn_v[oc] + 1e-5f);
        float sc = bn_g[oc] * rs;
        s_sc[tid] = sc;
        s_sh[tid] = hf ? (bn_b[oc] - bn_m[oc] * sc) : 0.f;
    }

    const int warp_m = wid >> 2;
    const int warp_n = wid & 3;

    const uint32_t sa = smem_u32(s_a);
    const uint32_t sb = smem_u32(s_b);

    float acc[4][4][4];
    #pragma unroll
    for (int mt = 0; mt < 4; mt++)
        #pragma unroll
        for (int nt = 0; nt < 4; nt++)
            #pragma unroll
            for (int q = 0; q < 4; q++) acc[mt][nt][q] = 0.f;

    const __half* Arow = g_xcol + (size_t)(node * NPX + tile * 128) * KDIM;

    const int a_row = warp_m * 64 + (lid & 15);
    const int a_kbh = lid >> 4;
    const int b_row = warp_n * 32 + (lid & 7) + ((lid >> 4) << 3);
    const int b_kbh = (lid >> 3) & 1;

    #pragma unroll
    for (int ck = 0; ck < 3; ck++) {
        const int ngroups = (ck == 2) ? 4 : 8;
        const int ksteps  = (ck == 2) ? 2 : 4;
        __syncthreads();
        for (int i = tid; i < 128 * ngroups; i += 256) {
            int g = i & (ngroups - 1);
            int r = i / ngroups;
            uint4 va = *(const uint4*)(Arow + (size_t)r * KDIM + ck * 64 + g * 8);
            *(uint4*)(s_a + sw128(r * 128 + g * 16)) = va;
            uint4 vb = *(const uint4*)(g_wcol + (size_t)r * KDIM + ck * 64 + g * 8);
            *(uint4*)(s_b + sw128(r * 128 + g * 16)) = vb;
        }
        __syncthreads();

        for (int s = 0; s < ksteps; s++) {
            uint32_t bf[4][2];
            #pragma unroll
            for (int np = 0; np < 2; np++) {
                uint32_t addr = sb + sw128((b_row + np * 16) * 128
                                           + (s * 2 + b_kbh) * 16);
                uint32_t r0, r1, r2, r3;
                ldsm_x4(r0, r1, r2, r3, addr);
                bf[np * 2][0] = r0;     bf[np * 2][1] = r1;
                bf[np * 2 + 1][0] = r2; bf[np * 2 + 1][1] = r3;
            }
            #pragma unroll
            for (int mt = 0; mt < 4; mt++) {
                uint32_t af[4];
                uint32_t addr = sa + sw128((a_row + mt * 16) * 128
                                           + (s * 2 + a_kbh) * 16);
                ldsm_x4(af[0], af[1], af[2], af[3], addr);
                #pragma unroll
                for (int nt = 0; nt < 4; nt++)
                    mma16816(acc[mt][nt], af, bf[nt]);
            }
        }
    }

    // ---- epilogue: BN fold -> fp16 g_convh ----
    const int g   = lid >> 2;
    const int tig = lid & 3;
    const int px0 = tile * 128 + warp_m * 64 + g;

    #pragma unroll
    for (int nt = 0; nt < 4; nt++) {
        int oc2a = warp_n * 32 + nt * 8 + tig * 2;
        #pragma unroll
        for (int half_c = 0; half_c < 2; half_c++) {
            int oc2 = oc2a + half_c;
            float sc = s_sc[oc2], sh = s_sh[oc2];
            int hf = oc2 >> 6, oc = oc2 & 63;
            __half* base = g_convh + ((size_t)(hf * 8 + node) * 64 + oc) * NPX;
            #pragma unroll
            for (int mt = 0; mt < 4; mt++) {
                int px = px0 + mt * 16;
                base[px]     = __float2half_rn(acc[mt][nt][half_c]     * sc + sh);
                base[px + 8] = __float2half_rn(acc[mt][nt][half_c + 2] * sc + sh);
            }
        }
    }
}

// ---------------------------------------------------------------------------
// Kernel 2: per-(pair, channel) fused A+B -> ReLU -> maxpool3x3s2p1 -> mean.
// half2 smem: s2[r][t] holds relu(a+b) for cols (2t-2, 2t-1); t=0 is pad.
// ---------------------------------------------------------------------------
__global__ __launch_bounds__(256) void pool_kernel()
{
    __shared__ __half2 s2[65][66];
    __shared__ float s_red[8];

    const int c   = blockIdx.x;
    const int tid = threadIdx.x;

    int p = blockIdx.y;           // 0..35 -> (i, j), i <= j
    int i = 0, base = 0;
    while (p >= base + (8 - i)) { base += 8 - i; i++; }
    int j = i + (p - base);

    const __half* pA = g_convh + ((size_t)(0 * 8 + i) * 64 + c) * NPX;
    const __half* pB = g_convh + ((size_t)(1 * 8 + j) * 64 + c) * NPX;

    const __half2 z2 = __floats2half2_rn(0.f, 0.f);
    float sum = 0.f;

    for (int phase = 0; phase < 2; phase++) {
        __syncthreads();
        const int gbase  = phase ? 63 : 0;
        const int sbase2 = phase ? 0 : 1;
        if (phase == 0)
            for (int q = tid; q < 66; q += 256) s2[0][q] = z2;   // top pad row
        for (int rr = tid; rr < 65; rr += 256) s2[rr][0] = z2;   // left pad

        const int nrows = phase ? 65 : 64;
        // stage: 32 half2-pairs per row (uint2 = 4 halfs = 2 half2)
        for (int t = tid; t < nrows * 32; t += 256) {
            int r  = t >> 5;
            int c4 = (t & 31) << 2;   // half index, 4 per iter
            uint2 av = *(const uint2*)(pA + (gbase + r) * 128 + c4);
            uint2 bv = *(const uint2*)(pB + (gbase + r) * 128 + c4);
            const __half2* ah = (const __half2*)&av;
            const __half2* bh = (const __half2*)&bv;
            __half2* d = &s2[sbase2 + r][1 + (c4 >> 1)];
            d[0] = __hmax2(__hadd2(ah[0], bh[0]), z2);
            d[1] = __hmax2(__hadd2(ah[1], bh[1]), z2);
        }
        __syncthreads();

        // 32 pool-output rows per phase
        for (int t = tid; t < 2048; t += 256) {
            int pyl = t >> 6;
            int po  = t & 63;
            int rb  = 2 * pyl;
            __half2 C = __hmax2(s2[rb][po + 1],
                        __hmax2(s2[rb + 1][po + 1], s2[rb + 2][po + 1]));
            __half2 L = __hmax2(s2[rb][po],
                        __hmax2(s2[rb + 1][po], s2[rb + 2][po]));
            __half m = __hmax(__hmax(__low2half(C), __high2half(C)),
                              __high2half(L));
            sum += __half2float(m);
        }
    }

    #pragma unroll
    for (int o = 16; o > 0; o >>= 1) sum += __shfl_down_sync(0xffffffffu, sum, o);
    if ((tid & 31) == 0) s_red[tid >> 5] = sum;
    __syncthreads();
    if (tid == 0) {
        float t = 0.f;
        #pragma unroll
        for (int q = 0; q < 8; q++) t += s_red[q];
        g_pooled[(i * 8 + j) * 64 + c] = t * (1.f / 4096.f);
    }
}

// ---------------------------------------------------------------------------
// Kernel 3: fc(64->1024)+ReLU, xyz/wpqr heads.
// ---------------------------------------------------------------------------
__global__ __launch_bounds__(256) void head_kernel(
    const int*   __restrict__ edge_index,
    const float* __restrict__ fc_w,   const float* __restrict__ fc_b,
    const float* __restrict__ xyz_w,  const float* __restrict__ xyz_b,
    const float* __restrict__ wpqr_w, const float* __restrict__ wpqr_b,
    float* __restrict__ out, int out_size)
{
    __shared__ float s_p[64];
    __shared__ float s_f[FEAT];
    __shared__ float s_red[6][8];

    const int e   = blockIdx.x;
    const int tid = threadIdx.x;

    int a0 = edge_index[e], a1 = edge_index[N_EDGES + e];
    int nmin = min(a0, a1), nmax = max(a0, a1);

    if (tid < 64) s_p[tid] = g_pooled[(nmin * 8 + nmax) * 64 + tid];
    __syncthreads();

    #pragma unroll
    for (int jj = 0; jj < 4; jj++) {
        int f = tid + jj * 256;
        float a = fc_b[f];
        const float* wr = fc_w + (size_t)f * 64;
        #pragma unroll 8
        for (int cc = 0; cc < 64; cc++) a += s_p[cc] * wr[cc];
        s_f[f] = fmaxf(a, 0.f);
    }
    __syncthreads();

    float p[6] = {0, 0, 0, 0, 0, 0};
    for (int f = tid; f < FEAT; f += 256) {
        float v = s_f[f];
        p[0] += v * xyz_w[f];
        p[1] += v * xyz_w[FEAT + f];
        p[2] += v * xyz_w[2 * FEAT + f];
        p[3] += v * wpqr_w[f];
        p[4] += v * wpqr_w[FEAT + f];
        p[5] += v * wpqr_w[2 * FEAT + f];
    }
    #pragma unroll
    for (int o = 0; o < 6; o++) {
        float v = p[o];
        #pragma unroll
        for (int sft = 16; sft > 0; sft >>= 1)
            v += __shfl_down_sync(0xffffffffu, v, sft);
        if ((tid & 31) == 0) s_red[o][tid >> 5] = v;
    }
    __syncthreads();
    if (tid < 6) {
        float t = 0.f;
        #pragma unroll
        for (int q = 0; q < 8; q++) t += s_red[tid][q];
        t += (tid < 3) ? xyz_b[tid] : wpqr_b[tid - 3];
        int offs = out_size - N_EDGES * 6;
        out[offs + e * 6 + tid] = t;
        if (e * 6 + tid < offs) out[e * 6 + tid] = t;
    }
}

// ---------------------------------------------------------------------------
extern "C" void kernel_launch(void* const* d_in, const int* in_sizes, int n_in,
                              void* d_out, int out_size)
{
    const float* x       = (const float*)d_in[0];
    const int*   ei      = (const int*)  d_in[1];
    const float* conv1_w = (const float*)d_in[2];
    const float* bn_g    = (const float*)d_in[3];
    const float* bn_b    = (const float*)d_in[4];
    const float* bn_m    = (const float*)d_in[5];
    const float* bn_v    = (const float*)d_in[6];
    const float* fc_w    = (const float*)d_in[7];
    const float* fc_b    = (const float*)d_in[8];
    const float* xyz_w   = (const float*)d_in[9];
    const float* xyz_b   = (const float*)d_in[10];
    const float* wpqr_w  = (const float*)d_in[11];
    const float* wpqr_b  = (const float*)d_in[12];
    float* out = (float*)d_out;

    im2col_kernel<<<dim3(128, 8), dim3(80, 4)>>>(x);
    wrepack_kernel<<<80, 256>>>(conv1_w);
    gemm_kernel<<<dim3(128, 8), 256>>>(bn_g, bn_b, bn_m, bn_v);
    pool_kernel<<<dim3(64, 36), 256>>>();
    head_kernel<<<N_EDGES, 256>>>(ei, fc_w, fc_b, xyz_w, xyz_b,
                                  wpqr_w, wpqr_b, out, out_size);
}

// round 8
// speedup vs baseline: 2.0489x; 1.0721x over previous
#include <cuda_runtime.h>
#include <cuda_fp16.h>
#include <cstdint>
#include <cstring>

#define HH 256
#define N_NODES 8
#define N_EDGES 64
#define FEAT 1024

#define KDIM 160            // 147 real taps padded to 10 k16-steps
#define KREAL 147
#define NPX 16384           // 128x128 output plane

// repacked weights (fp16): [oc2(128)][k(160)]   oc2 = half*64 + oc
__device__ __half g_wcol[128 * KDIM];
// BN-folded partial conv outputs (fp16): [half(2)][node(8)][oc(64)][128][128]
__device__ __half g_convh[(size_t)2 * 8 * 64 * 128 * 128];
// Pooled features per node-pair: [pair i*8+j][ch(64)]
__device__ float g_pooled[64 * 64];

__device__ __forceinline__ uint32_t smem_u32(const void* p) {
    uint32_t a;
    asm("{ .reg .u64 t; cvta.to.shared.u64 t, %1; cvt.u32.u64 %0, t; }"
        : "=r"(a) : "l"(p));
    return a;
}
__device__ __forceinline__ uint32_t sw128(uint32_t o) { return o ^ ((o >> 3) & 0x70); }

__device__ __forceinline__ void ldsm_x4(uint32_t& r0, uint32_t& r1,
                                        uint32_t& r2, uint32_t& r3, uint32_t a) {
    asm volatile("ldmatrix.sync.aligned.m8n8.x4.shared.b16 {%0,%1,%2,%3}, [%4];"
                 : "=r"(r0), "=r"(r1), "=r"(r2), "=r"(r3) : "r"(a));
}
__device__ __forceinline__ void mma16816(float* c, const uint32_t* a,
                                         const uint32_t* b) {
    asm volatile("mma.sync.aligned.m16n8k16.row.col.f32.f16.f16.f32 "
                 "{%0,%1,%2,%3}, {%4,%5,%6,%7}, {%8,%9}, {%0,%1,%2,%3};"
                 : "+f"(c[0]), "+f"(c[1]), "+f"(c[2]), "+f"(c[3])
                 : "r"(a[0]), "r"(a[1]), "r"(a[2]), "r"(a[3]),
                   "r"(b[0]), "r"(b[1]));
}

// ---------------------------------------------------------------------------
// Kernel 0: weight repack. Wcol[oc2][k], k = ci*49 + ky*7 + kx, pad->0.
// ---------------------------------------------------------------------------
__global__ __launch_bounds__(256) void wrepack_kernel(const float* __restrict__ w)
{
    for (int i = blockIdx.x * 256 + threadIdx.x; i < 128 * KDIM;
         i += gridDim.x * 256) {
        int oc2 = i / KDIM;
        int k   = i - oc2 * KDIM;
        int hf  = oc2 >> 6;
        int oc  = oc2 & 63;
        float val = 0.f;
        if (k < KREAL) {
            int ci = k / 49;
            int k2 = k - ci * 49;
            val = w[(oc * 6 + hf * 3 + ci) * 49 + k2];
        }
        g_wcol[i] = __float2half_rn(val);
    }
}

// ---------------------------------------------------------------------------
// Kernel 1: fused im2col + HMMA GEMM.  CTA = (py row, node).
// Stage input slab 3x7x264 fp16, build SW128 A chunks from it via tap table,
// B from g_wcol.  8 warps 2x4, warp tile 64x32, K=160 (64+64+32).
// Epilogue: BN fold -> padded smem -> coalesced uint4 copy-out to g_convh.
// ---------------------------------------------------------------------------
#define SLAB_N   5544          // 3*7*264 halfs
#define OFF_SC   0             // 128 f32
#define OFF_SH   512
#define OFF_OFF  1024          // 160 i32 tap offsets
#define OFF_SLAB 1664          // 5544 halfs = 11088 B -> ends 12752
#define OFF_A    12800         // 16384 B (SW128 chunk) ; also epi base
#define OFF_B    29184         // 16384 B
#define EPI_STRIDE 136         // halfs per oc2 row in epilogue
#define SMEM_TOT 47616         // OFF_A + 128*136*2 = 47616

__global__ __launch_bounds__(256) void gemm_kernel(
    const float* __restrict__ x,
    const float* __restrict__ bn_g, const float* __restrict__ bn_b,
    const float* __restrict__ bn_m, const float* __restrict__ bn_v)
{
    __shared__ __align__(128) char s_mem[SMEM_TOT];
    float* s_sc = (float*)(s_mem + OFF_SC);
    float* s_sh = (float*)(s_mem + OFF_SH);
    int*   s_off = (int*)(s_mem + OFF_OFF);
    __half* s_slab = (__half*)(s_mem + OFF_SLAB);
    char* s_a = s_mem + OFF_A;
    char* s_b = s_mem + OFF_B;

    const int tid  = threadIdx.x;
    const int wid  = tid >> 5;
    const int lid  = tid & 31;
    const int py   = blockIdx.x;          // output row 0..127
    const int node = blockIdx.y;

    // BN scale/shift
    if (tid < 128) {
        int hf = tid >> 6, oc = tid & 63;
        float rs = rsqrtf(bn_v[oc] + 1e-5f);
        float sc = bn_g[oc] * rs;
        s_sc[tid] = sc;
        s_sh[tid] = hf ? (bn_b[oc] - bn_m[oc] * sc) : 0.f;
    }
    // tap offset table: k -> slab half-index base (or -1 for pad)
    for (int k = tid; k < KDIM; k += 256) {
        int v = -1;
        if (k < KREAL) {
            int ci = k / 49;
            int rem = k - ci * 49;
            int ky = rem / 7;
            int kx = rem - ky * 7;
            v = (ci * 7 + ky) * 264 + kx;
        }
        s_off[k] = v;
    }
    // stage slab: input rows 2py-3..2py+3, cols -3..260, 3 channels
    for (int i = tid; i < SLAB_N; i += 256) {
        int ci  = i / (7 * 264);
        int rem = i - ci * (7 * 264);
        int ry  = rem / 264;
        int cc  = rem - ry * 264;
        int r = 2 * py - 3 + ry;
        int c = cc - 3;
        float v = 0.f;
        if (r >= 0 && r < HH && c >= 0 && c < HH)
            v = x[((size_t)(node * 3 + ci) * HH + r) * HH + c];
        s_slab[i] = __float2half_rn(v);
    }

    const int warp_m = wid >> 2;
    const int warp_n = wid & 3;
    const uint32_t sa = smem_u32(s_a);
    const uint32_t sb = smem_u32(s_b);

    float acc[4][4][4];
    #pragma unroll
    for (int mt = 0; mt < 4; mt++)
        #pragma unroll
        for (int nt = 0; nt < 4; nt++)
            #pragma unroll
            for (int q = 0; q < 4; q++) acc[mt][nt][q] = 0.f;

    const int a_row = warp_m * 64 + (lid & 15);
    const int a_kbh = lid >> 4;
    const int b_row = warp_n * 32 + (lid & 7) + ((lid >> 4) << 3);
    const int b_kbh = (lid >> 3) & 1;
    const __half hz = __ushort_as_half((unsigned short)0);

    #pragma unroll
    for (int ck = 0; ck < 3; ck++) {
        const int ngroups = (ck == 2) ? 4 : 8;
        const int ksteps  = (ck == 2) ? 2 : 4;
        __syncthreads();   // slab+table ready / previous chunk consumed
        for (int i = tid; i < 128 * ngroups; i += 256) {
            int g = i & (ngroups - 1);
            int r = i / ngroups;
            // build A group of 8 halfs from slab
            __align__(16) __half hv[8];
            #pragma unroll
            for (int q = 0; q < 8; q++) {
                int off = s_off[ck * 64 + g * 8 + q];
                hv[q] = (off >= 0) ? s_slab[off + 2 * r] : hz;
            }
            uint4 va;
            memcpy(&va, hv, 16);
            *(uint4*)(s_a + sw128(r * 128 + g * 16)) = va;
            uint4 vb = *(const uint4*)(g_wcol + (size_t)r * KDIM + ck * 64 + g * 8);
            *(uint4*)(s_b + sw128(r * 128 + g * 16)) = vb;
        }
        __syncthreads();

        for (int s = 0; s < ksteps; s++) {
            uint32_t bf[4][2];
            #pragma unroll
            for (int np = 0; np < 2; np++) {
                uint32_t addr = sb + sw128((b_row + np * 16) * 128
                                           + (s * 2 + b_kbh) * 16);
                uint32_t r0, r1, r2, r3;
                ldsm_x4(r0, r1, r2, r3, addr);
                bf[np * 2][0] = r0;     bf[np * 2][1] = r1;
                bf[np * 2 + 1][0] = r2; bf[np * 2 + 1][1] = r3;
            }
            #pragma unroll
            for (int mt = 0; mt < 4; mt++) {
                uint32_t af[4];
                uint32_t addr = sa + sw128((a_row + mt * 16) * 128
                                           + (s * 2 + a_kbh) * 16);
                ldsm_x4(af[0], af[1], af[2], af[3], addr);
                #pragma unroll
                for (int nt = 0; nt < 4; nt++)
                    mma16816(acc[mt][nt], af, bf[nt]);
            }
        }
    }

    // ---- epilogue: BN fold -> padded smem -> coalesced copy-out ----
    __syncthreads();                       // all warps done with s_a/s_b
    __half* epi = (__half*)(s_mem + OFF_A);
    const int g   = lid >> 2;
    const int tig = lid & 3;

    #pragma unroll
    for (int nt = 0; nt < 4; nt++) {
        #pragma unroll
        for (int half_c = 0; half_c < 2; half_c++) {
            int oc2 = warp_n * 32 + nt * 8 + tig * 2 + half_c;
            float sc = s_sc[oc2], sh = s_sh[oc2];
            #pragma unroll
            for (int mt = 0; mt < 4; mt++) {
                int pxl = warp_m * 64 + g + mt * 16;
                epi[oc2 * EPI_STRIDE + pxl] =
                    __float2half_rn(acc[mt][nt][half_c] * sc + sh);
                epi[oc2 * EPI_STRIDE + pxl + 8] =
                    __float2half_rn(acc[mt][nt][half_c + 2] * sc + sh);
            }
        }
    }
    __syncthreads();

    {
        int oc2 = tid >> 1, seg = tid & 1;
        int hf = oc2 >> 6, oc = oc2 & 63;
        __half* dst = g_convh + ((size_t)(hf * 8 + node) * 64 + oc) * NPX
                      + py * 128 + seg * 64;
        const uint4* src = (const uint4*)(epi + oc2 * EPI_STRIDE + seg * 64);
        #pragma unroll
        for (int q = 0; q < 8; q++)
            ((uint4*)dst)[q] = src[q];
    }
}

// ---------------------------------------------------------------------------
// Kernel 2: per-(pair, channel) pool.  Horizontal 3-max computed in registers
// at staging (left neighbor via shfl), hm stored one half per output col.
// Vertical 3-max + mean in second pass.  Zero-pad exact (relu >= 0).
// ---------------------------------------------------------------------------
__global__ __launch_bounds__(256) void pool_kernel()
{
    __shared__ __half s_hm[65][68];       // [row][output col], stride 68 halfs
    __shared__ float s_red[8];

    const int c   = blockIdx.x;
    const int tid = threadIdx.x;

    int p = blockIdx.y;           // 0..35 -> (i, j), i <= j
    int i = 0, base = 0;
    while (p >= base + (8 - i)) { base += 8 - i; i++; }
    int j = i + (p - base);

    const __half* pA = g_convh + ((size_t)(0 * 8 + i) * 64 + c) * NPX;
    const __half* pB = g_convh + ((size_t)(1 * 8 + j) * 64 + c) * NPX;

    const __half2 z2 = __floats2half2_rn(0.f, 0.f);
    float sum = 0.f;

    #pragma unroll
    for (int phase = 0; phase < 2; phase++) {
        __syncthreads();   // previous-phase vertical readers done
        const int gbase  = phase ? 63 : 0;
        const int sbase  = phase ? 0 : 1;
        const int nrows  = phase ? 65 : 64;
        if (phase == 0 && tid < 64) s_hm[0][tid] = __ushort_as_half(0);

        const int total = nrows * 16;
        const int iters = (total + 255) >> 8;
        for (int it = 0; it < iters; it++) {
            int t = it * 256 + tid;
            bool act = t < total;
            int r   = t >> 4;
            int c16 = t & 15;
            uint4 av = make_uint4(0, 0, 0, 0), bv = av;
            if (act) {
                av = *(const uint4*)(pA + (gbase + r) * 128 + c16 * 8);
                bv = *(const uint4*)(pB + (gbase + r) * 128 + c16 * 8);
            }
            const __half2* ah = (const __half2*)&av;
            const __half2* bh = (const __half2*)&bv;
            __half2 xx[4];
            #pragma unroll
            for (int q = 0; q < 4; q++)
                xx[q] = __hmax2(__hadd2(ah[q], bh[q]), z2);

            unsigned hi3 = __half_as_ushort(__high2half(xx[3]));
            unsigned left = __shfl_up_sync(0xffffffffu, hi3, 1);
            __half xl = (c16 == 0) ? __ushort_as_half(0)
                                   : __ushort_as_half((unsigned short)left);
            __half hm0 = __hmax(__hmax(__low2half(xx[0]), __high2half(xx[0])), xl);
            __half hm1 = __hmax(__hmax(__low2half(xx[1]), __high2half(xx[1])),
                                __high2half(xx[0]));
            __half hm2 = __hmax(__hmax(__low2half(xx[2]), __high2half(xx[2])),
                                __high2half(xx[1]));
            __half hm3 = __hmax(__hmax(__low2half(xx[3]), __high2half(xx[3])),
                                __high2half(xx[2]));
            if (act) {
                __align__(8) __half hv[4] = {hm0, hm1, hm2, hm3};
                uint2 bits;
                memcpy(&bits, hv, 8);
                *(uint2*)(&s_hm[sbase + r][c16 * 4]) = bits;
            }
        }
        __syncthreads();

        // vertical: 32 output rows x 32 half2 cols
        for (int t = tid; t < 1024; t += 256) {
            int pyl = t >> 5;
            int pop = t & 31;
            const __half2* r0 = (const __half2*)&s_hm[2 * pyl][0];
            const __half2* r1 = (const __half2*)&s_hm[2 * pyl + 1][0];
            const __half2* r2 = (const __half2*)&s_hm[2 * pyl + 2][0];
            __half2 m2 = __hmax2(r0[pop], __hmax2(r1[pop], r2[pop]));
            float2 f = __half22float2(m2);
            sum += f.x + f.y;
        }
    }

    #pragma unroll
    for (int o = 16; o > 0; o >>= 1) sum += __shfl_down_sync(0xffffffffu, sum, o);
    if ((tid & 31) == 0) s_red[tid >> 5] = sum;
    __syncthreads();
    if (tid == 0) {
        float t = 0.f;
        #pragma unroll
        for (int q = 0; q < 8; q++) t += s_red[q];
        g_pooled[(i * 8 + j) * 64 + c] = t * (1.f / 4096.f);
    }
}

// ---------------------------------------------------------------------------
// Kernel 3: fc(64->1024)+ReLU, xyz/wpqr heads.
// ---------------------------------------------------------------------------
__global__ __launch_bounds__(256) void head_kernel(
    const int*   __restrict__ edge_index,
    const float* __restrict__ fc_w,   const float* __restrict__ fc_b,
    const float* __restrict__ xyz_w,  const float* __restrict__ xyz_b,
    const float* __restrict__ wpqr_w, const float* __restrict__ wpqr_b,
    float* __restrict__ out, int out_size)
{
    __shared__ float s_p[64];
    __shared__ float s_f[FEAT];
    __shared__ float s_red[6][8];

    const int e   = blockIdx.x;
    const int tid = threadIdx.x;

    int a0 = edge_index[e], a1 = edge_index[N_EDGES + e];
    int nmin = min(a0, a1), nmax = max(a0, a1);

    if (tid < 64) s_p[tid] = g_pooled[(nmin * 8 + nmax) * 64 + tid];
    __syncthreads();

    #pragma unroll
    for (int jj = 0; jj < 4; jj++) {
        int f = tid + jj * 256;
        float a = fc_b[f];
        const float* wr = fc_w + (size_t)f * 64;
        #pragma unroll 8
        for (int cc = 0; cc < 64; cc++) a += s_p[cc] * wr[cc];
        s_f[f] = fmaxf(a, 0.f);
    }
    __syncthreads();

    float p[6] = {0, 0, 0, 0, 0, 0};
    for (int f = tid; f < FEAT; f += 256) {
        float v = s_f[f];
        p[0] += v * xyz_w[f];
        p[1] += v * xyz_w[FEAT + f];
        p[2] += v * xyz_w[2 * FEAT + f];
        p[3] += v * wpqr_w[f];
        p[4] += v * wpqr_w[FEAT + f];
        p[5] += v * wpqr_w[2 * FEAT + f];
    }
    #pragma unroll
    for (int o = 0; o < 6; o++) {
        float v = p[o];
        #pragma unroll
        for (int sft = 16; sft > 0; sft >>= 1)
            v += __shfl_down_sync(0xffffffffu, v, sft);
        if ((tid & 31) == 0) s_red[o][tid >> 5] = v;
    }
    __syncthreads();
    if (tid < 6) {
        float t = 0.f;
        #pragma unroll
        for (int q = 0; q < 8; q++) t += s_red[tid][q];
        t += (tid < 3) ? xyz_b[tid] : wpqr_b[tid - 3];
        int offs = out_size - N_EDGES * 6;
        out[offs + e * 6 + tid] = t;
        if (e * 6 + tid < offs) out[e * 6 + tid] = t;
    }
}

// ---------------------------------------------------------------------------
extern "C" void kernel_launch(void* const* d_in, const int* in_sizes, int n_in,
                              void* d_out, int out_size)
{
    const float* x       = (const float*)d_in[0];
    const int*   ei      = (const int*)  d_in[1];
    const float* conv1_w = (const float*)d_in[2];
    const float* bn_g    = (const float*)d_in[3];
    const float* bn_b    = (const float*)d_in[4];
    const float* bn_m    = (const float*)d_in[5];
    const float* bn_v    = (const float*)d_in[6];
    const float* fc_w    = (const float*)d_in[7];
    const float* fc_b    = (const float*)d_in[8];
    const float* xyz_w   = (const float*)d_in[9];
    const float* xyz_b   = (const float*)d_in[10];
    const float* wpqr_w  = (const float*)d_in[11];
    const float* wpqr_b  = (const float*)d_in[12];
    float* out = (float*)d_out;

    wrepack_kernel<<<80, 256>>>(conv1_w);
    gemm_kernel<<<dim3(128, 8), 256>>>(x, bn_g, bn_b, bn_m, bn_v);
    pool_kernel<<<dim3(64, 36), 256>>>();
    head_kernel<<<N_EDGES, 256>>>(ei, fc_w, fc_b, xyz_w, xyz_b,
                                  wpqr_w, wpqr_b, out, out_size);
}

// round 9
// speedup vs baseline: 2.8122x; 1.3725x over previous
#include <cuda_runtime.h>
#include <cuda_fp16.h>
#include <cstdint>
#include <cstring>

#define HH 256
#define N_NODES 8
#define N_EDGES 64
#define FEAT 1024

#define KDIM 160            // 147 real taps padded to 10 k16-steps
#define KREAL 147
#define NPX 16384           // 128x128 output plane

// repacked weights (fp16): [oc2(128)][k(160)]   oc2 = half*64 + oc
__device__ __half g_wcol[128 * KDIM];
// transposed fc weights: [cc(64)][f(1024)]
__device__ float g_fcT[64 * FEAT];
// BN-folded partial conv outputs (fp16): [half(2)][node(8)][oc(64)][128][128]
__device__ __half g_convh[(size_t)2 * 8 * 64 * 128 * 128];
// Pooled features per packed pair: [p(36)][ch(64)]
__device__ float g_pooled[36 * 64];
// FC features per packed pair: [p(36)][f(1024)]
__device__ float g_feat[36 * FEAT];
// Head outputs per packed pair: [p(36)][6]
__device__ float g_full[36 * 6];

__device__ __forceinline__ uint32_t smem_u32(const void* p) {
    uint32_t a;
    asm("{ .reg .u64 t; cvta.to.shared.u64 t, %1; cvt.u32.u64 %0, t; }"
        : "=r"(a) : "l"(p));
    return a;
}
__device__ __forceinline__ uint32_t sw128(uint32_t o) { return o ^ ((o >> 3) & 0x70); }

__device__ __forceinline__ void ldsm_x4(uint32_t& r0, uint32_t& r1,
                                        uint32_t& r2, uint32_t& r3, uint32_t a) {
    asm volatile("ldmatrix.sync.aligned.m8n8.x4.shared.b16 {%0,%1,%2,%3}, [%4];"
                 : "=r"(r0), "=r"(r1), "=r"(r2), "=r"(r3) : "r"(a));
}
__device__ __forceinline__ void mma16816(float* c, const uint32_t* a,
                                         const uint32_t* b) {
    asm volatile("mma.sync.aligned.m16n8k16.row.col.f32.f16.f16.f32 "
                 "{%0,%1,%2,%3}, {%4,%5,%6,%7}, {%8,%9}, {%0,%1,%2,%3};"
                 : "+f"(c[0]), "+f"(c[1]), "+f"(c[2]), "+f"(c[3])
                 : "r"(a[0]), "r"(a[1]), "r"(a[2]), "r"(a[3]),
                   "r"(b[0]), "r"(b[1]));
}

// ---------------------------------------------------------------------------
// Kernel 0: weight repack (conv weights -> fp16 Wcol) + fc_w transpose.
// ---------------------------------------------------------------------------
__global__ __launch_bounds__(256) void wrepack_kernel(
    const float* __restrict__ w, const float* __restrict__ fc_w)
{
    int gid = blockIdx.x * 256 + threadIdx.x;
    int stride = gridDim.x * 256;
    for (int i = gid; i < 128 * KDIM; i += stride) {
        int oc2 = i / KDIM;
        int k   = i - oc2 * KDIM;
        int hf  = oc2 >> 6;
        int oc  = oc2 & 63;
        float val = 0.f;
        if (k < KREAL) {
            int ci = k / 49;
            int k2 = k - ci * 49;
            val = w[(oc * 6 + hf * 3 + ci) * 49 + k2];
        }
        g_wcol[i] = __float2half_rn(val);
    }
    for (int i = gid; i < 64 * FEAT; i += stride) {
        int cc = i >> 10;
        int f  = i & (FEAT - 1);
        g_fcT[i] = fc_w[f * 64 + cc];
    }
}

// ---------------------------------------------------------------------------
// Kernel 1: fused im2col + HMMA GEMM.  CTA = (py row, node).
// ---------------------------------------------------------------------------
#define SLAB_N   5544          // 3*7*264 halfs
#define OFF_SC   0             // 128 f32
#define OFF_SH   512
#define OFF_OFF  1024          // 160 i32 tap offsets
#define OFF_SLAB 1664          // 5544 halfs = 11088 B
#define OFF_A    12800         // 16384 B (SW128 chunk) ; also epi base
#define OFF_B    29184         // 16384 B
#define EPI_STRIDE 136
#define SMEM_TOT 47616

__global__ __launch_bounds__(256) void gemm_kernel(
    const float* __restrict__ x,
    const float* __restrict__ bn_g, const float* __restrict__ bn_b,
    const float* __restrict__ bn_m, const float* __restrict__ bn_v)
{
    __shared__ __align__(128) char s_mem[SMEM_TOT];
    float* s_sc = (float*)(s_mem + OFF_SC);
    float* s_sh = (float*)(s_mem + OFF_SH);
    int*   s_off = (int*)(s_mem + OFF_OFF);
    __half* s_slab = (__half*)(s_mem + OFF_SLAB);
    char* s_a = s_mem + OFF_A;
    char* s_b = s_mem + OFF_B;

    const int tid  = threadIdx.x;
    const int wid  = tid >> 5;
    const int lid  = tid & 31;
    const int py   = blockIdx.x;
    const int node = blockIdx.y;

    if (tid < 128) {
        int hf = tid >> 6, oc = tid & 63;
        float rs = rsqrtf(bn_v[oc] + 1e-5f);
        float sc = bn_g[oc] * rs;
        s_sc[tid] = sc;
        s_sh[tid] = hf ? (bn_b[oc] - bn_m[oc] * sc) : 0.f;
    }
    for (int k = tid; k < KDIM; k += 256) {
        int v = -1;
        if (k < KREAL) {
            int ci = k / 49;
            int rem = k - ci * 49;
            int ky = rem / 7;
            int kx = rem - ky * 7;
            v = (ci * 7 + ky) * 264 + kx;
        }
        s_off[k] = v;
    }
    for (int i = tid; i < SLAB_N; i += 256) {
        int ci  = i / (7 * 264);
        int rem = i - ci * (7 * 264);
        int ry  = rem / 264;
        int cc  = rem - ry * 264;
        int r = 2 * py - 3 + ry;
        int c = cc - 3;
        float v = 0.f;
        if (r >= 0 && r < HH && c >= 0 && c < HH)
            v = x[((size_t)(node * 3 + ci) * HH + r) * HH + c];
        s_slab[i] = __float2half_rn(v);
    }

    const int warp_m = wid >> 2;
    const int warp_n = wid & 3;
    const uint32_t sa = smem_u32(s_a);
    const uint32_t sb = smem_u32(s_b);

    float acc[4][4][4];
    #pragma unroll
    for (int mt = 0; mt < 4; mt++)
        #pragma unroll
        for (int nt = 0; nt < 4; nt++)
            #pragma unroll
            for (int q = 0; q < 4; q++) acc[mt][nt][q] = 0.f;

    const int a_row = warp_m * 64 + (lid & 15);
    const int a_kbh = lid >> 4;
    const int b_row = warp_n * 32 + (lid & 7) + ((lid >> 4) << 3);
    const int b_kbh = (lid >> 3) & 1;
    const __half hz = __ushort_as_half((unsigned short)0);

    #pragma unroll
    for (int ck = 0; ck < 3; ck++) {
        const int ngroups = (ck == 2) ? 4 : 8;
        const int ksteps  = (ck == 2) ? 2 : 4;
        __syncthreads();
        for (int i = tid; i < 128 * ngroups; i += 256) {
            int g = i & (ngroups - 1);
            int r = i / ngroups;
            __align__(16) __half hv[8];
            #pragma unroll
            for (int q = 0; q < 8; q++) {
                int off = s_off[ck * 64 + g * 8 + q];
                hv[q] = (off >= 0) ? s_slab[off + 2 * r] : hz;
            }
            uint4 va;
            memcpy(&va, hv, 16);
            *(uint4*)(s_a + sw128(r * 128 + g * 16)) = va;
            uint4 vb = *(const uint4*)(g_wcol + (size_t)r * KDIM + ck * 64 + g * 8);
            *(uint4*)(s_b + sw128(r * 128 + g * 16)) = vb;
        }
        __syncthreads();

        for (int s = 0; s < ksteps; s++) {
            uint32_t bf[4][2];
            #pragma unroll
            for (int np = 0; np < 2; np++) {
                uint32_t addr = sb + sw128((b_row + np * 16) * 128
                                           + (s * 2 + b_kbh) * 16);
                uint32_t r0, r1, r2, r3;
                ldsm_x4(r0, r1, r2, r3, addr);
                bf[np * 2][0] = r0;     bf[np * 2][1] = r1;
                bf[np * 2 + 1][0] = r2; bf[np * 2 + 1][1] = r3;
            }
            #pragma unroll
            for (int mt = 0; mt < 4; mt++) {
                uint32_t af[4];
                uint32_t addr = sa + sw128((a_row + mt * 16) * 128
                                           + (s * 2 + a_kbh) * 16);
                ldsm_x4(af[0], af[1], af[2], af[3], addr);
                #pragma unroll
                for (int nt = 0; nt < 4; nt++)
                    mma16816(acc[mt][nt], af, bf[nt]);
            }
        }
    }

    __syncthreads();
    __half* epi = (__half*)(s_mem + OFF_A);
    const int g   = lid >> 2;
    const int tig = lid & 3;

    #pragma unroll
    for (int nt = 0; nt < 4; nt++) {
        #pragma unroll
        for (int half_c = 0; half_c < 2; half_c++) {
            int oc2 = warp_n * 32 + nt * 8 + tig * 2 + half_c;
            float sc = s_sc[oc2], sh = s_sh[oc2];
            #pragma unroll
            for (int mt = 0; mt < 4; mt++) {
                int pxl = warp_m * 64 + g + mt * 16;
                epi[oc2 * EPI_STRIDE + pxl] =
                    __float2half_rn(acc[mt][nt][half_c] * sc + sh);
                epi[oc2 * EPI_STRIDE + pxl + 8] =
                    __float2half_rn(acc[mt][nt][half_c + 2] * sc + sh);
            }
        }
    }
    __syncthreads();

    {
        int oc2 = tid >> 1, seg = tid & 1;
        int hf = oc2 >> 6, oc = oc2 & 63;
        __half* dst = g_convh + ((size_t)(hf * 8 + node) * 64 + oc) * NPX
                      + py * 128 + seg * 64;
        const uint4* src = (const uint4*)(epi + oc2 * EPI_STRIDE + seg * 64);
        #pragma unroll
        for (int q = 0; q < 8; q++)
            ((uint4*)dst)[q] = src[q];
    }
}

// ---------------------------------------------------------------------------
// Kernel 2: per-(pair, channel) pool.  Horizontal 3-max at staging,
// vertical 3-max + mean second pass.
// ---------------------------------------------------------------------------
__global__ __launch_bounds__(256) void pool_kernel()
{
    __shared__ __half s_hm[65][68];
    __shared__ float s_red[8];

    const int c   = blockIdx.x;
    const int tid = threadIdx.x;

    int p = blockIdx.y;           // packed 0..35 -> (i, j), i <= j
    int i = 0, base = 0;
    while (p >= base + (8 - i)) { base += 8 - i; i++; }
    int j = i + (p - base);

    const __half* pA = g_convh + ((size_t)(0 * 8 + i) * 64 + c) * NPX;
    const __half* pB = g_convh + ((size_t)(1 * 8 + j) * 64 + c) * NPX;

    const __half2 z2 = __floats2half2_rn(0.f, 0.f);
    float sum = 0.f;

    #pragma unroll
    for (int phase = 0; phase < 2; phase++) {
        __syncthreads();
        const int gbase  = phase ? 63 : 0;
        const int sbase  = phase ? 0 : 1;
        const int nrows  = phase ? 65 : 64;
        if (phase == 0 && tid < 64) s_hm[0][tid] = __ushort_as_half(0);

        const int total = nrows * 16;
        const int iters = (total + 255) >> 8;
        for (int it = 0; it < iters; it++) {
            int t = it * 256 + tid;
            bool act = t < total;
            int r   = t >> 4;
            int c16 = t & 15;
            uint4 av = make_uint4(0, 0, 0, 0), bv = av;
            if (act) {
                av = *(const uint4*)(pA + (gbase + r) * 128 + c16 * 8);
                bv = *(const uint4*)(pB + (gbase + r) * 128 + c16 * 8);
            }
            const __half2* ah = (const __half2*)&av;
            const __half2* bh = (const __half2*)&bv;
            __half2 xx[4];
            #pragma unroll
            for (int q = 0; q < 4; q++)
                xx[q] = __hmax2(__hadd2(ah[q], bh[q]), z2);

            unsigned hi3 = __half_as_ushort(__high2half(xx[3]));
            unsigned left = __shfl_up_sync(0xffffffffu, hi3, 1);
            __half xl = (c16 == 0) ? __ushort_as_half(0)
                                   : __ushort_as_half((unsigned short)left);
            __half hm0 = __hmax(__hmax(__low2half(xx[0]), __high2half(xx[0])), xl);
            __half hm1 = __hmax(__hmax(__low2half(xx[1]), __high2half(xx[1])),
                                __high2half(xx[0]));
            __half hm2 = __hmax(__hmax(__low2half(xx[2]), __high2half(xx[2])),
                                __high2half(xx[1]));
            __half hm3 = __hmax(__hmax(__low2half(xx[3]), __high2half(xx[3])),
                                __high2half(xx[2]));
            if (act) {
                __align__(8) __half hv[4] = {hm0, hm1, hm2, hm3};
                uint2 bits;
                memcpy(&bits, hv, 8);
                *(uint2*)(&s_hm[sbase + r][c16 * 4]) = bits;
            }
        }
        __syncthreads();

        for (int t = tid; t < 1024; t += 256) {
            int pyl = t >> 5;
            int pop = t & 31;
            const __half2* r0 = (const __half2*)&s_hm[2 * pyl][0];
            const __half2* r1 = (const __half2*)&s_hm[2 * pyl + 1][0];
            const __half2* r2 = (const __half2*)&s_hm[2 * pyl + 2][0];
            __half2 m2 = __hmax2(r0[pop], __hmax2(r1[pop], r2[pop]));
            float2 f = __half22float2(m2);
            sum += f.x + f.y;
        }
    }

    #pragma unroll
    for (int o = 16; o > 0; o >>= 1) sum += __shfl_down_sync(0xffffffffu, sum, o);
    if ((tid & 31) == 0) s_red[tid >> 5] = sum;
    __syncthreads();
    if (tid == 0) {
        float t = 0.f;
        #pragma unroll
        for (int q = 0; q < 8; q++) t += s_red[q];
        g_pooled[p * 64 + c] = t * (1.f / 4096.f);
    }
}

// ---------------------------------------------------------------------------
// Kernel 3a: fc(64->1024)+ReLU per packed pair.  grid (4, 36), 256 thr.
// Coalesced g_fcT reads (feature contiguous).
// ---------------------------------------------------------------------------
__global__ __launch_bounds__(256) void fc_kernel(const float* __restrict__ fc_b)
{
    __shared__ float s_p[64];
    const int p   = blockIdx.y;
    const int f   = blockIdx.x * 256 + threadIdx.x;
    if (threadIdx.x < 64) s_p[threadIdx.x] = g_pooled[p * 64 + threadIdx.x];
    __syncthreads();

    float a = fc_b[f];
    #pragma unroll
    for (int cc = 0; cc < 64; cc++)
        a += s_p[cc] * g_fcT[cc * FEAT + f];
    g_feat[p * FEAT + f] = fmaxf(a, 0.f);
}

// ---------------------------------------------------------------------------
// Kernel 3b: heads (1024 -> 6) per packed pair.  grid 36, 256 thr.
// ---------------------------------------------------------------------------
__global__ __launch_bounds__(256) void heads_kernel(
    const float* __restrict__ xyz_w,  const float* __restrict__ xyz_b,
    const float* __restrict__ wpqr_w, const float* __restrict__ wpqr_b)
{
    __shared__ float s_f[FEAT];
    __shared__ float s_red[6][8];

    const int pp  = blockIdx.x;
    const int tid = threadIdx.x;

    #pragma unroll
    for (int q = 0; q < 4; q++)
        s_f[tid + q * 256] = g_feat[pp * FEAT + tid + q * 256];
    __syncthreads();

    float acc[6] = {0, 0, 0, 0, 0, 0};
    #pragma unroll
    for (int q = 0; q < 4; q++) {
        int f = tid + q * 256;
        float v = s_f[f];
        acc[0] += v * xyz_w[f];
        acc[1] += v * xyz_w[FEAT + f];
        acc[2] += v * xyz_w[2 * FEAT + f];
        acc[3] += v * wpqr_w[f];
        acc[4] += v * wpqr_w[FEAT + f];
        acc[5] += v * wpqr_w[2 * FEAT + f];
    }
    #pragma unroll
    for (int o = 0; o < 6; o++) {
        float v = acc[o];
        #pragma unroll
        for (int sft = 16; sft > 0; sft >>= 1)
            v += __shfl_down_sync(0xffffffffu, v, sft);
        if ((tid & 31) == 0) s_red[o][tid >> 5] = v;
    }
    __syncthreads();
    if (tid < 6) {
        float t = 0.f;
        #pragma unroll
        for (int q = 0; q < 8; q++) t += s_red[tid][q];
        t += (tid < 3) ? xyz_b[tid] : wpqr_b[tid - 3];
        g_full[pp * 6 + tid] = t;
    }
}

// ---------------------------------------------------------------------------
// Kernel 3c: scatter to output.  out[0:offs) = full[:offs/6], out[offs:] = full.
// ---------------------------------------------------------------------------
__global__ __launch_bounds__(512) void scatter_kernel(
    const int* __restrict__ edge_index, float* __restrict__ out, int out_size)
{
    int idx = threadIdx.x;
    if (idx >= out_size) return;
    int offs = out_size - N_EDGES * 6;
    int rel = (idx < offs) ? idx : idx - offs;
    int e = rel / 6, o = rel - e * 6;
    int a0 = edge_index[e], a1 = edge_index[N_EDGES + e];
    int i = min(a0, a1), j = max(a0, a1);
    int pk = 8 * i - (i * (i - 1)) / 2 + (j - i);
    out[idx] = g_full[pk * 6 + o];
}

// ---------------------------------------------------------------------------
extern "C" void kernel_launch(void* const* d_in, const int* in_sizes, int n_in,
                              void* d_out, int out_size)
{
    const float* x       = (const float*)d_in[0];
    const int*   ei      = (const int*)  d_in[1];
    const float* conv1_w = (const float*)d_in[2];
    const float* bn_g    = (const float*)d_in[3];
    const float* bn_b    = (const float*)d_in[4];
    const float* bn_m    = (const float*)d_in[5];
    const float* bn_v    = (const float*)d_in[6];
    const float* fc_w    = (const float*)d_in[7];
    const float* fc_b    = (const float*)d_in[8];
    const float* xyz_w   = (const float*)d_in[9];
    const float* xyz_b   = (const float*)d_in[10];
    const float* wpqr_w  = (const float*)d_in[11];
    const float* wpqr_b  = (const float*)d_in[12];
    float* out = (float*)d_out;

    wrepack_kernel<<<336, 256>>>(conv1_w, fc_w);
    gemm_kernel<<<dim3(128, 8), 256>>>(x, bn_g, bn_b, bn_m, bn_v);
    pool_kernel<<<dim3(64, 36), 256>>>();
    fc_kernel<<<dim3(4, 36), 256>>>(fc_b);
    heads_kernel<<<36, 256>>>(xyz_w, xyz_b, wpqr_w, wpqr_b);
    scatter_kernel<<<1, 512>>>(ei, out, out_size);
}

// round 10
// speedup vs baseline: 3.0196x; 1.0737x over previous
#include <cuda_runtime.h>
#include <cuda_fp16.h>
#include <cstdint>
#include <cstring>

#define HH 256
#define N_NODES 8
#define N_EDGES 64
#define FEAT 1024

#define KDIM 160            // 147 real taps padded to 10 k16-steps
#define KREAL 147
#define NPX 16384           // 128x128 output plane

// repacked weights (fp16): [oc2(128)][k(160)]
__device__ __align__(16) __half g_wcol[128 * KDIM];
// transposed fc weights: [cc(64)][f(1024)]
__device__ float g_fcT[64 * FEAT];
// BN-folded partial conv outputs (fp16): [half(2)][node(8)][oc(64)][128][128]
__device__ __half g_convh[(size_t)2 * 8 * 64 * 128 * 128];
// Pooled features per packed pair: [p(36)][ch(64)]
__device__ float g_pooled[36 * 64];

__device__ __forceinline__ uint32_t smem_u32(const void* p) {
    uint32_t a;
    asm("{ .reg .u64 t; cvta.to.shared.u64 t, %1; cvt.u32.u64 %0, t; }"
        : "=r"(a) : "l"(p));
    return a;
}
__device__ __forceinline__ uint32_t sw128(uint32_t o) { return o ^ ((o >> 3) & 0x70); }

__device__ __forceinline__ void ldsm_x4(uint32_t& r0, uint32_t& r1,
                                        uint32_t& r2, uint32_t& r3, uint32_t a) {
    asm volatile("ldmatrix.sync.aligned.m8n8.x4.shared.b16 {%0,%1,%2,%3}, [%4];"
                 : "=r"(r0), "=r"(r1), "=r"(r2), "=r"(r3) : "r"(a));
}
__device__ __forceinline__ void mma16816(float* c, const uint32_t* a,
                                         const uint32_t* b) {
    asm volatile("mma.sync.aligned.m16n8k16.row.col.f32.f16.f16.f32 "
                 "{%0,%1,%2,%3}, {%4,%5,%6,%7}, {%8,%9}, {%0,%1,%2,%3};"
                 : "+f"(c[0]), "+f"(c[1]), "+f"(c[2]), "+f"(c[3])
                 : "r"(a[0]), "r"(a[1]), "r"(a[2]), "r"(a[3]),
                   "r"(b[0]), "r"(b[1]));
}
#define CP_COMMIT() asm volatile("cp.async.commit_group;" ::: "memory")
#define CP_WAIT0()  asm volatile("cp.async.wait_group 0;" ::: "memory")

// ---------------------------------------------------------------------------
// Kernel 0: weight repack (conv -> fp16 Wcol) + fc_w transpose.
// ---------------------------------------------------------------------------
__global__ __launch_bounds__(256) void wrepack_kernel(
    const float* __restrict__ w, const float* __restrict__ fc_w)
{
    int gid = blockIdx.x * 256 + threadIdx.x;
    int stride = gridDim.x * 256;
    for (int i = gid; i < 128 * KDIM; i += stride) {
        int oc2 = i / KDIM;
        int k   = i - oc2 * KDIM;
        int hf  = oc2 >> 6;
        int oc  = oc2 & 63;
        float val = 0.f;
        if (k < KREAL) {
            int ci = k / 49;
            int k2 = k - ci * 49;
            val = w[(oc * 6 + hf * 3 + ci) * 49 + k2];
        }
        g_wcol[i] = __float2half_rn(val);
    }
    for (int i = gid; i < 64 * FEAT; i += stride) {
        int cc = i >> 10;
        int f  = i & (FEAT - 1);
        g_fcT[i] = fc_w[f * 64 + cc];
    }
}

// ---------------------------------------------------------------------------
// Kernel 1: fused im2col + HMMA GEMM, double-buffered K chunks.
// CTA = (py row, node).  A built from smem slab, B via cp.async from g_wcol.
// ---------------------------------------------------------------------------
#define SLAB_N    5544
#define DOFF_SC   0
#define DOFF_SH   512
#define DOFF_OFF  1024
#define DOFF_SLAB 1664          // 11088 B -> ends 12752
#define DOFF_A0   12800
#define DOFF_A1   29184
#define DOFF_B0   45568
#define DOFF_B1   61952
#define DSMEM_TOT 78336
#define EPI_STRIDE 136          // epi region: DOFF_A0 + 34816 <= 47616 (in B0)

__device__ __forceinline__ void build_chunk(
    int ck, char* s_a, uint32_t sb_u, const __half* s_slab,
    const int* s_off, int tid, __half hz)
{
    const int full = (ck != 2);
    const int n = full ? 1024 : 512;
    for (int i = tid; i < n; i += 256) {
        int g = full ? (i & 7) : (i & 3);
        int r = full ? (i >> 3) : (i >> 2);
        __align__(16) __half hv[8];
        #pragma unroll
        for (int q = 0; q < 8; q++) {
            int off = s_off[ck * 64 + g * 8 + q];
            hv[q] = (off >= 0) ? s_slab[off + 2 * r] : hz;
        }
        uint4 va;
        memcpy(&va, hv, 16);
        *(uint4*)(s_a + sw128(r * 128 + g * 16)) = va;
        const void* src = g_wcol + (size_t)r * KDIM + ck * 64 + g * 8;
        asm volatile("cp.async.cg.shared.global [%0], [%1], 16;"
                     :: "r"(sb_u + sw128(r * 128 + g * 16)), "l"(src));
    }
}

__device__ __forceinline__ void mma_chunk(
    uint32_t sa, uint32_t sb, int ksteps, float (&acc)[4][4][4],
    int a_row, int a_kbh, int b_row, int b_kbh)
{
    for (int s = 0; s < ksteps; s++) {
        uint32_t bf[4][2];
        #pragma unroll
        for (int np = 0; np < 2; np++) {
            uint32_t addr = sb + sw128((b_row + np * 16) * 128
                                       + (s * 2 + b_kbh) * 16);
            uint32_t r0, r1, r2, r3;
            ldsm_x4(r0, r1, r2, r3, addr);
            bf[np * 2][0] = r0;     bf[np * 2][1] = r1;
            bf[np * 2 + 1][0] = r2; bf[np * 2 + 1][1] = r3;
        }
        #pragma unroll
        for (int mt = 0; mt < 4; mt++) {
            uint32_t af[4];
            uint32_t addr = sa + sw128((a_row + mt * 16) * 128
                                       + (s * 2 + a_kbh) * 16);
            ldsm_x4(af[0], af[1], af[2], af[3], addr);
            #pragma unroll
            for (int nt = 0; nt < 4; nt++)
                mma16816(acc[mt][nt], af, bf[nt]);
        }
    }
}

__global__ __launch_bounds__(256, 2) void gemm_kernel(
    const float* __restrict__ x,
    const float* __restrict__ bn_g, const float* __restrict__ bn_b,
    const float* __restrict__ bn_m, const float* __restrict__ bn_v)
{
    extern __shared__ __align__(128) char dsm[];
    float* s_sc = (float*)(dsm + DOFF_SC);
    float* s_sh = (float*)(dsm + DOFF_SH);
    int*   s_off = (int*)(dsm + DOFF_OFF);
    __half* s_slab = (__half*)(dsm + DOFF_SLAB);
    char* sa0 = dsm + DOFF_A0;
    char* sa1 = dsm + DOFF_A1;
    const uint32_t sau0 = smem_u32(sa0);
    const uint32_t sau1 = smem_u32(sa1);
    const uint32_t sbu0 = smem_u32(dsm + DOFF_B0);
    const uint32_t sbu1 = smem_u32(dsm + DOFF_B1);

    const int tid  = threadIdx.x;
    const int wid  = tid >> 5;
    const int lid  = tid & 31;
    const int py   = blockIdx.x;
    const int node = blockIdx.y;

    if (tid < 128) {
        int hf = tid >> 6, oc = tid & 63;
        float rs = rsqrtf(bn_v[oc] + 1e-5f);
        float sc = bn_g[oc] * rs;
        s_sc[tid] = sc;
        s_sh[tid] = hf ? (bn_b[oc] - bn_m[oc] * sc) : 0.f;
    }
    for (int k = tid; k < KDIM; k += 256) {
        int v = -1;
        if (k < KREAL) {
            int ci = k / 49;
            int rem = k - ci * 49;
            int ky = rem / 7;
            int kx = rem - ky * 7;
            v = (ci * 7 + ky) * 264 + kx;
        }
        s_off[k] = v;
    }
    for (int i = tid; i < SLAB_N; i += 256) {
        int ci  = i / (7 * 264);
        int rem = i - ci * (7 * 264);
        int ry  = rem / 264;
        int cc  = rem - ry * 264;
        int r = 2 * py - 3 + ry;
        int c = cc - 3;
        float v = 0.f;
        if (r >= 0 && r < HH && c >= 0 && c < HH)
            v = x[((size_t)(node * 3 + ci) * HH + r) * HH + c];
        s_slab[i] = __float2half_rn(v);
    }

    const int warp_m = wid >> 2;
    const int warp_n = wid & 3;

    float acc[4][4][4];
    #pragma unroll
    for (int mt = 0; mt < 4; mt++)
        #pragma unroll
        for (int nt = 0; nt < 4; nt++)
            #pragma unroll
            for (int q = 0; q < 4; q++) acc[mt][nt][q] = 0.f;

    const int a_row = warp_m * 64 + (lid & 15);
    const int a_kbh = lid >> 4;
    const int b_row = warp_n * 32 + (lid & 7) + ((lid >> 4) << 3);
    const int b_kbh = (lid >> 3) & 1;
    const __half hz = __ushort_as_half((unsigned short)0);

    __syncthreads();                      // slab + table ready
    build_chunk(0, sa0, sbu0, s_slab, s_off, tid, hz);
    CP_COMMIT();
    CP_WAIT0();
    __syncthreads();

    // ck = 0: build 1 into buf1, mma on buf0
    build_chunk(1, sa1, sbu1, s_slab, s_off, tid, hz);
    CP_COMMIT();
    mma_chunk(sau0, sbu0, 4, acc, a_row, a_kbh, b_row, b_kbh);
    CP_WAIT0();
    __syncthreads();

    // ck = 1: build 2 into buf0, mma on buf1
    build_chunk(2, sa0, sbu0, s_slab, s_off, tid, hz);
    CP_COMMIT();
    mma_chunk(sau1, sbu1, 4, acc, a_row, a_kbh, b_row, b_kbh);
    CP_WAIT0();
    __syncthreads();

    // ck = 2: mma on buf0 (half chunk)
    mma_chunk(sau0, sbu0, 2, acc, a_row, a_kbh, b_row, b_kbh);

    // ---- epilogue: BN fold -> padded smem -> coalesced copy-out ----
    __syncthreads();
    __half* epi = (__half*)(dsm + DOFF_A0);
    const int g   = lid >> 2;
    const int tig = lid & 3;

    #pragma unroll
    for (int nt = 0; nt < 4; nt++) {
        #pragma unroll
        for (int half_c = 0; half_c < 2; half_c++) {
            int oc2 = warp_n * 32 + nt * 8 + tig * 2 + half_c;
            float sc = s_sc[oc2], sh = s_sh[oc2];
            #pragma unroll
            for (int mt = 0; mt < 4; mt++) {
                int pxl = warp_m * 64 + g + mt * 16;
                epi[oc2 * EPI_STRIDE + pxl] =
                    __float2half_rn(acc[mt][nt][half_c] * sc + sh);
                epi[oc2 * EPI_STRIDE + pxl + 8] =
                    __float2half_rn(acc[mt][nt][half_c + 2] * sc + sh);
            }
        }
    }
    __syncthreads();

    {
        int oc2 = tid >> 1, seg = tid & 1;
        int hf = oc2 >> 6, oc = oc2 & 63;
        __half* dst = g_convh + ((size_t)(hf * 8 + node) * 64 + oc) * NPX
                      + py * 128 + seg * 64;
        const uint4* src = (const uint4*)(epi + oc2 * EPI_STRIDE + seg * 64);
        #pragma unroll
        for (int q = 0; q < 8; q++)
            ((uint4*)dst)[q] = src[q];
    }
}

// ---------------------------------------------------------------------------
// Kernel 2: per-(pair, channel) pool.  Horizontal 3-max at staging,
// vertical 3-max + mean second pass.
// ---------------------------------------------------------------------------
__global__ __launch_bounds__(256) void pool_kernel()
{
    __shared__ __half s_hm[65][68];
    __shared__ float s_red[8];

    const int c   = blockIdx.x;
    const int tid = threadIdx.x;

    int p = blockIdx.y;           // packed 0..35 -> (i, j), i <= j
    int i = 0, base = 0;
    while (p >= base + (8 - i)) { base += 8 - i; i++; }
    int j = i + (p - base);

    const __half* pA = g_convh + ((size_t)(0 * 8 + i) * 64 + c) * NPX;
    const __half* pB = g_convh + ((size_t)(1 * 8 + j) * 64 + c) * NPX;

    const __half2 z2 = __floats2half2_rn(0.f, 0.f);
    float sum = 0.f;

    #pragma unroll
    for (int phase = 0; phase < 2; phase++) {
        __syncthreads();
        const int gbase  = phase ? 63 : 0;
        const int sbase  = phase ? 0 : 1;
        const int nrows  = phase ? 65 : 64;
        if (phase == 0 && tid < 64) s_hm[0][tid] = __ushort_as_half(0);

        const int total = nrows * 16;
        const int iters = (total + 255) >> 8;
        for (int it = 0; it < iters; it++) {
            int t = it * 256 + tid;
            bool act = t < total;
            int r   = t >> 4;
            int c16 = t & 15;
            uint4 av = make_uint4(0, 0, 0, 0), bv = av;
            if (act) {
                av = *(const uint4*)(pA + (gbase + r) * 128 + c16 * 8);
                bv = *(const uint4*)(pB + (gbase + r) * 128 + c16 * 8);
            }
            const __half2* ah = (const __half2*)&av;
            const __half2* bh = (const __half2*)&bv;
            __half2 xx[4];
            #pragma unroll
            for (int q = 0; q < 4; q++)
                xx[q] = __hmax2(__hadd2(ah[q], bh[q]), z2);

            unsigned hi3 = __half_as_ushort(__high2half(xx[3]));
            unsigned left = __shfl_up_sync(0xffffffffu, hi3, 1);
            __half xl = (c16 == 0) ? __ushort_as_half(0)
                                   : __ushort_as_half((unsigned short)left);
            __half hm0 = __hmax(__hmax(__low2half(xx[0]), __high2half(xx[0])), xl);
            __half hm1 = __hmax(__hmax(__low2half(xx[1]), __high2half(xx[1])),
                                __high2half(xx[0]));
            __half hm2 = __hmax(__hmax(__low2half(xx[2]), __high2half(xx[2])),
                                __high2half(xx[1]));
            __half hm3 = __hmax(__hmax(__low2half(xx[3]), __high2half(xx[3])),
                                __high2half(xx[2]));
            if (act) {
                __align__(8) __half hv[4] = {hm0, hm1, hm2, hm3};
                uint2 bits;
                memcpy(&bits, hv, 8);
                *(uint2*)(&s_hm[sbase + r][c16 * 4]) = bits;
            }
        }
        __syncthreads();

        for (int t = tid; t < 1024; t += 256) {
            int pyl = t >> 5;
            int pop = t & 31;
            const __half2* r0 = (const __half2*)&s_hm[2 * pyl][0];
            const __half2* r1 = (const __half2*)&s_hm[2 * pyl + 1][0];
            const __half2* r2 = (const __half2*)&s_hm[2 * pyl + 2][0];
            __half2 m2 = __hmax2(r0[pop], __hmax2(r1[pop], r2[pop]));
            float2 f = __half22float2(m2);
            sum += f.x + f.y;
        }
    }

    #pragma unroll
    for (int o = 16; o > 0; o >>= 1) sum += __shfl_down_sync(0xffffffffu, sum, o);
    if ((tid & 31) == 0) s_red[tid >> 5] = sum;
    __syncthreads();
    if (tid == 0) {
        float t = 0.f;
        #pragma unroll
        for (int q = 0; q < 8; q++) t += s_red[q];
        g_pooled[p * 64 + c] = t * (1.f / 4096.f);
    }
}

// ---------------------------------------------------------------------------
// Kernel 3: fused fc(64->1024)+ReLU -> heads(1024->6) -> edge scatter.
// One block per packed pair (36 blocks).
// ---------------------------------------------------------------------------
__global__ __launch_bounds__(256) void head_all_kernel(
    const int*   __restrict__ edge_index, const float* __restrict__ fc_b,
    const float* __restrict__ xyz_w,  const float* __restrict__ xyz_b,
    const float* __restrict__ wpqr_w, const float* __restrict__ wpqr_b,
    float* __restrict__ out, int out_size)
{
    __shared__ float s_p[64];
    __shared__ float s_f[FEAT];
    __shared__ float s_red[6][8];
    __shared__ float s_out[6];

    const int pp  = blockIdx.x;
    const int tid = threadIdx.x;

    if (tid < 64) s_p[tid] = g_pooled[pp * 64 + tid];
    __syncthreads();

    #pragma unroll
    for (int q = 0; q < 4; q++) {
        int f = tid + q * 256;
        float a = fc_b[f];
        #pragma unroll 8
        for (int cc = 0; cc < 64; cc++)
            a += s_p[cc] * g_fcT[cc * FEAT + f];
        s_f[f] = fmaxf(a, 0.f);
    }
    __syncthreads();

    float acc[6] = {0, 0, 0, 0, 0, 0};
    #pragma unroll
    for (int q = 0; q < 4; q++) {
        int f = tid + q * 256;
        float v = s_f[f];
        acc[0] += v * xyz_w[f];
        acc[1] += v * xyz_w[FEAT + f];
        acc[2] += v * xyz_w[2 * FEAT + f];
        acc[3] += v * wpqr_w[f];
        acc[4] += v * wpqr_w[FEAT + f];
        acc[5] += v * wpqr_w[2 * FEAT + f];
    }
    #pragma unroll
    for (int o = 0; o < 6; o++) {
        float v = acc[o];
        #pragma unroll
        for (int sft = 16; sft > 0; sft >>= 1)
            v += __shfl_down_sync(0xffffffffu, v, sft);
        if ((tid & 31) == 0) s_red[o][tid >> 5] = v;
    }
    __syncthreads();
    if (tid < 6) {
        float t = 0.f;
        #pragma unroll
        for (int q = 0; q < 8; q++) t += s_red[tid][q];
        t += (tid < 3) ? xyz_b[tid] : wpqr_b[tid - 3];
        s_out[tid] = t;
    }
    __syncthreads();

    // scatter: each block writes output elements whose edge maps to pair pp
    int offs = out_size - N_EDGES * 6;
    for (int idx = tid; idx < out_size; idx += 256) {
        int rel = (idx < offs) ? idx : idx - offs;
        int e = rel / 6, o = rel - e * 6;
        int a0 = edge_index[e], a1 = edge_index[N_EDGES + e];
        int i = min(a0, a1), j = max(a0, a1);
        int pk = 8 * i - (i * (i - 1)) / 2 + (j - i);
        if (pk == pp) out[idx] = s_out[o];
    }
}

// ---------------------------------------------------------------------------
extern "C" void kernel_launch(void* const* d_in, const int* in_sizes, int n_in,
                              void* d_out, int out_size)
{
    const float* x       = (const float*)d_in[0];
    const int*   ei      = (const int*)  d_in[1];
    const float* conv1_w = (const float*)d_in[2];
    const float* bn_g    = (const float*)d_in[3];
    const float* bn_b    = (const float*)d_in[4];
    const float* bn_m    = (const float*)d_in[5];
    const float* bn_v    = (const float*)d_in[6];
    const float* fc_w    = (const float*)d_in[7];
    const float* fc_b    = (const float*)d_in[8];
    const float* xyz_w   = (const float*)d_in[9];
    const float* xyz_b   = (const float*)d_in[10];
    const float* wpqr_w  = (const float*)d_in[11];
    const float* wpqr_b  = (const float*)d_in[12];
    float* out = (float*)d_out;

    cudaFuncSetAttribute(gemm_kernel,
                         cudaFuncAttributeMaxDynamicSharedMemorySize, DSMEM_TOT);

    wrepack_kernel<<<336, 256>>>(conv1_w, fc_w);
    gemm_kernel<<<dim3(128, 8), 256, DSMEM_TOT>>>(x, bn_g, bn_b, bn_m, bn_v);
    pool_kernel<<<dim3(64, 36), 256>>>();
    head_all_kernel<<<36, 256>>>(ei, fc_b, xyz_w, xyz_b, wpqr_w, wpqr_b,
                                 out, out_size);
}

// round 11
// speedup vs baseline: 3.4071x; 1.1283x over previous
#include <cuda_runtime.h>
#include <cuda_fp16.h>
#include <cstdint>
#include <cstring>

#define HH 256
#define N_NODES 8
#define N_EDGES 64
#define FEAT 1024

#define KDIM 160            // 147 real taps padded to 10 k16-steps
#define KREAL 147
#define NPX 16384           // 128x128 output plane

// repacked weights (fp16): [oc2(128)][k(160)]
__device__ __align__(16) __half g_wcol[128 * KDIM];
// transposed fc weights: [cc(64)][f(1024)]
__device__ float g_fcT[64 * FEAT];
// BN-folded partial conv outputs (fp16): [half(2)][node(8)][oc(64)][128][128]
__device__ __half g_convh[(size_t)2 * 8 * 64 * 128 * 128];
// Pooled features per packed pair: [p(36)][ch(64)]
__device__ float g_pooled[36 * 64];
// FC features per packed pair: [p(36)][f(1024)]
__device__ float g_feat[36 * FEAT];

__device__ __forceinline__ uint32_t smem_u32(const void* p) {
    uint32_t a;
    asm("{ .reg .u64 t; cvta.to.shared.u64 t, %1; cvt.u32.u64 %0, t; }"
        : "=r"(a) : "l"(p));
    return a;
}
__device__ __forceinline__ uint32_t sw128(uint32_t o) { return o ^ ((o >> 3) & 0x70); }

__device__ __forceinline__ void ldsm_x4(uint32_t& r0, uint32_t& r1,
                                        uint32_t& r2, uint32_t& r3, uint32_t a) {
    asm volatile("ldmatrix.sync.aligned.m8n8.x4.shared.b16 {%0,%1,%2,%3}, [%4];"
                 : "=r"(r0), "=r"(r1), "=r"(r2), "=r"(r3) : "r"(a));
}
__device__ __forceinline__ void mma16816(float* c, const uint32_t* a,
                                         const uint32_t* b) {
    asm volatile("mma.sync.aligned.m16n8k16.row.col.f32.f16.f16.f32 "
                 "{%0,%1,%2,%3}, {%4,%5,%6,%7}, {%8,%9}, {%0,%1,%2,%3};"
                 : "+f"(c[0]), "+f"(c[1]), "+f"(c[2]), "+f"(c[3])
                 : "r"(a[0]), "r"(a[1]), "r"(a[2]), "r"(a[3]),
                   "r"(b[0]), "r"(b[1]));
}
#define CP_COMMIT() asm volatile("cp.async.commit_group;" ::: "memory")
#define CP_WAIT0()  asm volatile("cp.async.wait_group 0;" ::: "memory")

// ---------------------------------------------------------------------------
// Kernel 0: weight repack (conv -> fp16 Wcol) + fc_w transpose.
// ---------------------------------------------------------------------------
__global__ __launch_bounds__(256) void wrepack_kernel(
    const float* __restrict__ w, const float* __restrict__ fc_w)
{
    int gid = blockIdx.x * 256 + threadIdx.x;
    int stride = gridDim.x * 256;
    for (int i = gid; i < 128 * KDIM; i += stride) {
        int oc2 = i / KDIM;
        int k   = i - oc2 * KDIM;
        int hf  = oc2 >> 6;
        int oc  = oc2 & 63;
        float val = 0.f;
        if (k < KREAL) {
            int ci = k / 49;
            int k2 = k - ci * 49;
            val = w[(oc * 6 + hf * 3 + ci) * 49 + k2];
        }
        g_wcol[i] = __float2half_rn(val);
    }
    for (int i = gid; i < 64 * FEAT; i += stride) {
        int cc = i >> 10;
        int f  = i & (FEAT - 1);
        g_fcT[i] = fc_w[f * 64 + cc];
    }
}

// ---------------------------------------------------------------------------
// Kernel 1: fused im2col + HMMA GEMM, double-buffered K chunks.
// ---------------------------------------------------------------------------
#define SLAB_N    5544
#define DOFF_SC   0
#define DOFF_SH   512
#define DOFF_OFF  1024
#define DOFF_SLAB 1664
#define DOFF_A0   12800
#define DOFF_A1   29184
#define DOFF_B0   45568
#define DOFF_B1   61952
#define DSMEM_TOT 78336
#define EPI_STRIDE 136

__device__ __forceinline__ void build_chunk(
    int ck, char* s_a, uint32_t sb_u, const __half* s_slab,
    const int* s_off, int tid, __half hz)
{
    const int full = (ck != 2);
    const int n = full ? 1024 : 512;
    for (int i = tid; i < n; i += 256) {
        int g = full ? (i & 7) : (i & 3);
        int r = full ? (i >> 3) : (i >> 2);
        __align__(16) __half hv[8];
        #pragma unroll
        for (int q = 0; q < 8; q++) {
            int off = s_off[ck * 64 + g * 8 + q];
            hv[q] = (off >= 0) ? s_slab[off + 2 * r] : hz;
        }
        uint4 va;
        memcpy(&va, hv, 16);
        *(uint4*)(s_a + sw128(r * 128 + g * 16)) = va;
        const void* src = g_wcol + (size_t)r * KDIM + ck * 64 + g * 8;
        asm volatile("cp.async.cg.shared.global [%0], [%1], 16;"
                     :: "r"(sb_u + sw128(r * 128 + g * 16)), "l"(src));
    }
}

__device__ __forceinline__ void mma_chunk(
    uint32_t sa, uint32_t sb, int ksteps, float (&acc)[4][4][4],
    int a_row, int a_kbh, int b_row, int b_kbh)
{
    for (int s = 0; s < ksteps; s++) {
        uint32_t bf[4][2];
        #pragma unroll
        for (int np = 0; np < 2; np++) {
            uint32_t addr = sb + sw128((b_row + np * 16) * 128
                                       + (s * 2 + b_kbh) * 16);
            uint32_t r0, r1, r2, r3;
            ldsm_x4(r0, r1, r2, r3, addr);
            bf[np * 2][0] = r0;     bf[np * 2][1] = r1;
            bf[np * 2 + 1][0] = r2; bf[np * 2 + 1][1] = r3;
        }
        #pragma unroll
        for (int mt = 0; mt < 4; mt++) {
            uint32_t af[4];
            uint32_t addr = sa + sw128((a_row + mt * 16) * 128
                                       + (s * 2 + a_kbh) * 16);
            ldsm_x4(af[0], af[1], af[2], af[3], addr);
            #pragma unroll
            for (int nt = 0; nt < 4; nt++)
                mma16816(acc[mt][nt], af, bf[nt]);
        }
    }
}

__global__ __launch_bounds__(256, 2) void gemm_kernel(
    const float* __restrict__ x,
    const float* __restrict__ bn_g, const float* __restrict__ bn_b,
    const float* __restrict__ bn_m, const float* __restrict__ bn_v)
{
    extern __shared__ __align__(128) char dsm[];
    float* s_sc = (float*)(dsm + DOFF_SC);
    float* s_sh = (float*)(dsm + DOFF_SH);
    int*   s_off = (int*)(dsm + DOFF_OFF);
    __half* s_slab = (__half*)(dsm + DOFF_SLAB);
    char* sa0 = dsm + DOFF_A0;
    char* sa1 = dsm + DOFF_A1;
    const uint32_t sau0 = smem_u32(sa0);
    const uint32_t sau1 = smem_u32(sa1);
    const uint32_t sbu0 = smem_u32(dsm + DOFF_B0);
    const uint32_t sbu1 = smem_u32(dsm + DOFF_B1);

    const int tid  = threadIdx.x;
    const int wid  = tid >> 5;
    const int lid  = tid & 31;
    const int py   = blockIdx.x;
    const int node = blockIdx.y;

    if (tid < 128) {
        int hf = tid >> 6, oc = tid & 63;
        float rs = rsqrtf(bn_v[oc] + 1e-5f);
        float sc = bn_g[oc] * rs;
        s_sc[tid] = sc;
        s_sh[tid] = hf ? (bn_b[oc] - bn_m[oc] * sc) : 0.f;
    }
    for (int k = tid; k < KDIM; k += 256) {
        int v = -1;
        if (k < KREAL) {
            int ci = k / 49;
            int rem = k - ci * 49;
            int ky = rem / 7;
            int kx = rem - ky * 7;
            v = (ci * 7 + ky) * 264 + kx;
        }
        s_off[k] = v;
    }
    for (int i = tid; i < SLAB_N; i += 256) {
        int ci  = i / (7 * 264);
        int rem = i - ci * (7 * 264);
        int ry  = rem / 264;
        int cc  = rem - ry * 264;
        int r = 2 * py - 3 + ry;
        int c = cc - 3;
        float v = 0.f;
        if (r >= 0 && r < HH && c >= 0 && c < HH)
            v = x[((size_t)(node * 3 + ci) * HH + r) * HH + c];
        s_slab[i] = __float2half_rn(v);
    }

    const int warp_m = wid >> 2;
    const int warp_n = wid & 3;

    float acc[4][4][4];
    #pragma unroll
    for (int mt = 0; mt < 4; mt++)
        #pragma unroll
        for (int nt = 0; nt < 4; nt++)
            #pragma unroll
            for (int q = 0; q < 4; q++) acc[mt][nt][q] = 0.f;

    const int a_row = warp_m * 64 + (lid & 15);
    const int a_kbh = lid >> 4;
    const int b_row = warp_n * 32 + (lid & 7) + ((lid >> 4) << 3);
    const int b_kbh = (lid >> 3) & 1;
    const __half hz = __ushort_as_half((unsigned short)0);

    __syncthreads();
    build_chunk(0, sa0, sbu0, s_slab, s_off, tid, hz);
    CP_COMMIT();
    CP_WAIT0();
    __syncthreads();

    build_chunk(1, sa1, sbu1, s_slab, s_off, tid, hz);
    CP_COMMIT();
    mma_chunk(sau0, sbu0, 4, acc, a_row, a_kbh, b_row, b_kbh);
    CP_WAIT0();
    __syncthreads();

    build_chunk(2, sa0, sbu0, s_slab, s_off, tid, hz);
    CP_COMMIT();
    mma_chunk(sau1, sbu1, 4, acc, a_row, a_kbh, b_row, b_kbh);
    CP_WAIT0();
    __syncthreads();

    mma_chunk(sau0, sbu0, 2, acc, a_row, a_kbh, b_row, b_kbh);

    // ---- epilogue ----
    __syncthreads();
    __half* epi = (__half*)(dsm + DOFF_A0);
    const int g   = lid >> 2;
    const int tig = lid & 3;

    #pragma unroll
    for (int nt = 0; nt < 4; nt++) {
        #pragma unroll
        for (int half_c = 0; half_c < 2; half_c++) {
            int oc2 = warp_n * 32 + nt * 8 + tig * 2 + half_c;
            float sc = s_sc[oc2], sh = s_sh[oc2];
            #pragma unroll
            for (int mt = 0; mt < 4; mt++) {
                int pxl = warp_m * 64 + g + mt * 16;
                epi[oc2 * EPI_STRIDE + pxl] =
                    __float2half_rn(acc[mt][nt][half_c] * sc + sh);
                epi[oc2 * EPI_STRIDE + pxl + 8] =
                    __float2half_rn(acc[mt][nt][half_c + 2] * sc + sh);
            }
        }
    }
    __syncthreads();

    {
        int oc2 = tid >> 1, seg = tid & 1;
        int hf = oc2 >> 6, oc = oc2 & 63;
        __half* dst = g_convh + ((size_t)(hf * 8 + node) * 64 + oc) * NPX
                      + py * 128 + seg * 64;
        const uint4* src = (const uint4*)(epi + oc2 * EPI_STRIDE + seg * 64);
        #pragma unroll
        for (int q = 0; q < 8; q++)
            ((uint4*)dst)[q] = src[q];
    }
}

// ---------------------------------------------------------------------------
// Kernel 2: per-(pair, channel) pool.
// ---------------------------------------------------------------------------
__global__ __launch_bounds__(256) void pool_kernel()
{
    __shared__ __half s_hm[65][68];
    __shared__ float s_red[8];

    const int c   = blockIdx.x;
    const int tid = threadIdx.x;

    int p = blockIdx.y;
    int i = 0, base = 0;
    while (p >= base + (8 - i)) { base += 8 - i; i++; }
    int j = i + (p - base);

    const __half* pA = g_convh + ((size_t)(0 * 8 + i) * 64 + c) * NPX;
    const __half* pB = g_convh + ((size_t)(1 * 8 + j) * 64 + c) * NPX;

    const __half2 z2 = __floats2half2_rn(0.f, 0.f);
    float sum = 0.f;

    #pragma unroll
    for (int phase = 0; phase < 2; phase++) {
        __syncthreads();
        const int gbase  = phase ? 63 : 0;
        const int sbase  = phase ? 0 : 1;
        const int nrows  = phase ? 65 : 64;
        if (phase == 0 && tid < 64) s_hm[0][tid] = __ushort_as_half(0);

        const int total = nrows * 16;
        const int iters = (total + 255) >> 8;
        for (int it = 0; it < iters; it++) {
            int t = it * 256 + tid;
            bool act = t < total;
            int r   = t >> 4;
            int c16 = t & 15;
            uint4 av = make_uint4(0, 0, 0, 0), bv = av;
            if (act) {
                av = *(const uint4*)(pA + (gbase + r) * 128 + c16 * 8);
                bv = *(const uint4*)(pB + (gbase + r) * 128 + c16 * 8);
            }
            const __half2* ah = (const __half2*)&av;
            const __half2* bh = (const __half2*)&bv;
            __half2 xx[4];
            #pragma unroll
            for (int q = 0; q < 4; q++)
                xx[q] = __hmax2(__hadd2(ah[q], bh[q]), z2);

            unsigned hi3 = __half_as_ushort(__high2half(xx[3]));
            unsigned left = __shfl_up_sync(0xffffffffu, hi3, 1);
            __half xl = (c16 == 0) ? __ushort_as_half(0)
                                   : __ushort_as_half((unsigned short)left);
            __half hm0 = __hmax(__hmax(__low2half(xx[0]), __high2half(xx[0])), xl);
            __half hm1 = __hmax(__hmax(__low2half(xx[1]), __high2half(xx[1])),
                                __high2half(xx[0]));
            __half hm2 = __hmax(__hmax(__low2half(xx[2]), __high2half(xx[2])),
                                __high2half(xx[1]));
            __half hm3 = __hmax(__hmax(__low2half(xx[3]), __high2half(xx[3])),
                                __high2half(xx[2]));
            if (act) {
                __align__(8) __half hv[4] = {hm0, hm1, hm2, hm3};
                uint2 bits;
                memcpy(&bits, hv, 8);
                *(uint2*)(&s_hm[sbase + r][c16 * 4]) = bits;
            }
        }
        __syncthreads();

        for (int t = tid; t < 1024; t += 256) {
            int pyl = t >> 5;
            int pop = t & 31;
            const __half2* r0 = (const __half2*)&s_hm[2 * pyl][0];
            const __half2* r1 = (const __half2*)&s_hm[2 * pyl + 1][0];
            const __half2* r2 = (const __half2*)&s_hm[2 * pyl + 2][0];
            __half2 m2 = __hmax2(r0[pop], __hmax2(r1[pop], r2[pop]));
            float2 f = __half22float2(m2);
            sum += f.x + f.y;
        }
    }

    #pragma unroll
    for (int o = 16; o > 0; o >>= 1) sum += __shfl_down_sync(0xffffffffu, sum, o);
    if ((tid & 31) == 0) s_red[tid >> 5] = sum;
    __syncthreads();
    if (tid == 0) {
        float t = 0.f;
        #pragma unroll
        for (int q = 0; q < 8; q++) t += s_red[q];
        g_pooled[p * 64 + c] = t * (1.f / 4096.f);
    }
}

// ---------------------------------------------------------------------------
// Kernel 3a: fc(64->1024)+ReLU per packed pair.  grid (4, 36), 256 thr.
// ---------------------------------------------------------------------------
__global__ __launch_bounds__(256) void fc_kernel(const float* __restrict__ fc_b)
{
    __shared__ float s_p[64];
    const int p = blockIdx.y;
    const int f = blockIdx.x * 256 + threadIdx.x;
    if (threadIdx.x < 64) s_p[threadIdx.x] = g_pooled[p * 64 + threadIdx.x];
    __syncthreads();

    float a = fc_b[f];
    #pragma unroll
    for (int cc = 0; cc < 64; cc++)
        a += s_p[cc] * g_fcT[cc * FEAT + f];
    g_feat[p * FEAT + f] = fmaxf(a, 0.f);
}

// ---------------------------------------------------------------------------
// Kernel 3b: heads (1024->6) + edge scatter.  grid 36, 256 thr.
// ---------------------------------------------------------------------------
__global__ __launch_bounds__(256) void heads_scatter_kernel(
    const int*   __restrict__ edge_index,
    const float* __restrict__ xyz_w,  const float* __restrict__ xyz_b,
    const float* __restrict__ wpqr_w, const float* __restrict__ wpqr_b,
    float* __restrict__ out, int out_size)
{
    __shared__ float s_f[FEAT];
    __shared__ float s_red[6][8];
    __shared__ float s_out[6];

    const int pp  = blockIdx.x;
    const int tid = threadIdx.x;

    #pragma unroll
    for (int q = 0; q < 4; q++)
        s_f[tid + q * 256] = g_feat[pp * FEAT + tid + q * 256];
    __syncthreads();

    float acc[6] = {0, 0, 0, 0, 0, 0};
    #pragma unroll
    for (int q = 0; q < 4; q++) {
        int f = tid + q * 256;
        float v = s_f[f];
        acc[0] += v * xyz_w[f];
        acc[1] += v * xyz_w[FEAT + f];
        acc[2] += v * xyz_w[2 * FEAT + f];
        acc[3] += v * wpqr_w[f];
        acc[4] += v * wpqr_w[FEAT + f];
        acc[5] += v * wpqr_w[2 * FEAT + f];
    }
    #pragma unroll
    for (int o = 0; o < 6; o++) {
        float v = acc[o];
        #pragma unroll
        for (int sft = 16; sft > 0; sft >>= 1)
            v += __shfl_down_sync(0xffffffffu, v, sft);
        if ((tid & 31) == 0) s_red[o][tid >> 5] = v;
    }
    __syncthreads();
    if (tid < 6) {
        float t = 0.f;
        #pragma unroll
        for (int q = 0; q < 8; q++) t += s_red[tid][q];
        t += (tid < 3) ? xyz_b[tid] : wpqr_b[tid - 3];
        s_out[tid] = t;
    }
    __syncthreads();

    int offs = out_size - N_EDGES * 6;
    for (int idx = tid; idx < out_size; idx += 256) {
        int rel = (idx < offs) ? idx : idx - offs;
        int e = rel / 6, o = rel - e * 6;
        int a0 = edge_index[e], a1 = edge_index[N_EDGES + e];
        int i = min(a0, a1), j = max(a0, a1);
        int pk = 8 * i - (i * (i - 1)) / 2 + (j - i);
        if (pk == pp) out[idx] = s_out[o];
    }
}

// ---------------------------------------------------------------------------
extern "C" void kernel_launch(void* const* d_in, const int* in_sizes, int n_in,
                              void* d_out, int out_size)
{
    const float* x       = (const float*)d_in[0];
    const int*   ei      = (const int*)  d_in[1];
    const float* conv1_w = (const float*)d_in[2];
    const float* bn_g    = (const float*)d_in[3];
    const float* bn_b    = (const float*)d_in[4];
    const float* bn_m    = (const float*)d_in[5];
    const float* bn_v    = (const float*)d_in[6];
    const float* fc_w    = (const float*)d_in[7];
    const float* fc_b    = (const float*)d_in[8];
    const float* xyz_w   = (const float*)d_in[9];
    const float* xyz_b   = (const float*)d_in[10];
    const float* wpqr_w  = (const float*)d_in[11];
    const float* wpqr_b  = (const float*)d_in[12];
    float* out = (float*)d_out;

    cudaFuncSetAttribute(gemm_kernel,
                         cudaFuncAttributeMaxDynamicSharedMemorySize, DSMEM_TOT);

    wrepack_kernel<<<336, 256>>>(conv1_w, fc_w);
    gemm_kernel<<<dim3(128, 8), 256, DSMEM_TOT>>>(x, bn_g, bn_b, bn_m, bn_v);
    pool_kernel<<<dim3(64, 36), 256>>>();
    fc_kernel<<<dim3(4, 36), 256>>>(fc_b);
    heads_scatter_kernel<<<36, 256>>>(ei, xyz_w, xyz_b, wpqr_w, wpqr_b,
                                      out, out_size);
}